// round 13
// baseline (speedup 1.0000x reference)
#include <cuda_runtime.h>
#include <cuda_fp16.h>
#include <mma.h>
using namespace nvcuda;

#define NN 50000
#define EE 850000
#define NTILES 782   // ceil(NN/64)
#define PGRID 444

// ---------------- scratch (device globals) ----------------------------------
__device__ float  g_h0[NN * 128];
__device__ float  g_h1[NN * 128];
__device__ __half g_feath[NN * 128];
__device__ float  g_el[NN * 4];
__device__ float  g_er[NN * 4];
__device__ int    g_deg[NN];
__device__ int    g_rowptr[NN + 1];
__device__ int    g_cursor[NN];
__device__ int    g_csr[EE];
__device__ float  g_bnstat[3 * 256];

__device__ __forceinline__ float eluf(float x) { return x > 0.f ? x : (__expf(x) - 1.f); }
__device__ __forceinline__ float lrelu(float x) { return x > 0.f ? x : 0.2f * x; }

__device__ __forceinline__ void split2h(float v, __half& hi, __half& lo) {
    hi = __float2half_rn(v);
    lo = __float2half_rn(v - __half2float(hi));
}

// ---------------- CSR build --------------------------------------------------
__global__ void k_hist(const int* __restrict__ dst, int* deg) {
    int i = blockIdx.x * blockDim.x + threadIdx.x;
    if (i < EE) atomicAdd(&deg[dst[i]], 1);
}

// Single-block scan over all NN degrees: writes rowptr[0..NN] and cursor[0..NN).
__global__ void k_scan_all(const int* __restrict__ deg, int* __restrict__ rowptr,
                           int* __restrict__ cursor) {
    __shared__ int ws[32];
    __shared__ int carry;
    int t = threadIdx.x, lane = t & 31, w = t >> 5;   // 1024 threads, 32 warps
    if (t == 0) carry = 0;
    __syncthreads();
    for (int base = 0; base < NN; base += 1024) {
        int idx = base + t;
        int v = (idx < NN) ? deg[idx] : 0;
        int incl = v;
#pragma unroll
        for (int o = 1; o < 32; o <<= 1) {
            int u = __shfl_up_sync(0xffffffffu, incl, o);
            if (lane >= o) incl += u;
        }
        if (lane == 31) ws[w] = incl;
        __syncthreads();
        if (w == 0) {
            int s = ws[lane];
#pragma unroll
            for (int o = 1; o < 32; o <<= 1) {
                int u = __shfl_up_sync(0xffffffffu, s, o);
                if (lane >= o) s += u;
            }
            ws[lane] = s;   // inclusive warp-sums
        }
        __syncthreads();
        int woff = (w > 0) ? ws[w - 1] : 0;
        int res = carry + woff + incl - v;   // global exclusive prefix
        if (idx < NN) { rowptr[idx] = res; cursor[idx] = res; }
        __syncthreads();
        if (t == 0) carry += ws[31];
        __syncthreads();
    }
    if (t == 0) rowptr[NN] = carry;
}

__global__ void k_fill(const int* __restrict__ src, const int* __restrict__ dst,
                       int* cursor, int* __restrict__ csr) {
    int i = blockIdx.x * blockDim.x + threadIdx.x;
    if (i < EE) {
        int d = dst[i];
        int pos = atomicAdd(&cursor[d], 1);
        csr[pos] = src[i];
    }
}

// ---------------- persistent HMMA GEMM (64-row tiles) + fused el/er ----------
template <bool L0>
__global__ void k_gemm(const float* __restrict__ A, const int* __restrict__ xidx,
                       const float* __restrict__ embed, const float* __restrict__ W,
                       const float* __restrict__ stat, const float* __restrict__ gamma,
                       const float* __restrict__ beta, const float* __restrict__ alv,
                       const float* __restrict__ arv, __half* __restrict__ feat,
                       float* __restrict__ el, float* __restrict__ er) {
    extern __shared__ __half smh[];
    __half* sW   = smh;                    // 128 x 136
    __half* sAhi = sW + 128 * 136;         // 64 x 136
    __half* sAlo = sAhi + 64 * 136;        // 64 x 136
    __shared__ float sc[128], shf[128];
    __shared__ float s_al[128], s_ar[128];
    int tid = threadIdx.x, warp = tid >> 5;

    if (!L0) {
        if (tid < 128) {
            float mu = stat[tid] * (1.f / NN);
            float var = stat[128 + tid] * (1.f / NN) - mu * mu;
            float r = rsqrtf(var + 1e-5f);
            sc[tid] = gamma[tid] * r;
            shf[tid] = beta[tid] - mu * gamma[tid] * r;
        }
    }
    if (tid < 128) { s_al[tid] = alv[tid]; s_ar[tid] = arv[tid]; }

    for (int p = tid; p < 4096; p += 256) {
        int r = p >> 5, c = (p & 31) * 4;
        float4 v = *(const float4*)&W[(size_t)r * 128 + c];
        sW[r * 136 + c]     = __float2half_rn(v.x);
        sW[r * 136 + c + 1] = __float2half_rn(v.y);
        sW[r * 136 + c + 2] = __float2half_rn(v.z);
        sW[r * 136 + c + 3] = __float2half_rn(v.w);
    }

    int mrow = (warp & 3) * 16;
    int ncol = (warp >> 2) * 64;

    for (int tile = blockIdx.x; tile < NTILES; tile += gridDim.x) {
        int row0 = tile * 64;
        __syncthreads();   // W ready / stage consumed
        for (int p = tid; p < 2048; p += 256) {
            int row = p >> 5, c = (p & 31) * 4;
            int gr = row0 + row;
            float4 v = make_float4(0.f, 0.f, 0.f, 0.f);
            if (gr < NN) {
                if (L0) v = *(const float4*)&embed[(size_t)xidx[gr] * 128 + c];
                else {
                    v = *(const float4*)&A[(size_t)gr * 128 + c];
                    v.x = eluf(v.x * sc[c] + shf[c]);
                    v.y = eluf(v.y * sc[c + 1] + shf[c + 1]);
                    v.z = eluf(v.z * sc[c + 2] + shf[c + 2]);
                    v.w = eluf(v.w * sc[c + 3] + shf[c + 3]);
                }
            }
            split2h(v.x, sAhi[row * 136 + c], sAlo[row * 136 + c]);
            split2h(v.y, sAhi[row * 136 + c + 1], sAlo[row * 136 + c + 1]);
            split2h(v.z, sAhi[row * 136 + c + 2], sAlo[row * 136 + c + 2]);
            split2h(v.w, sAhi[row * 136 + c + 3], sAlo[row * 136 + c + 3]);
        }
        __syncthreads();

        wmma::fragment<wmma::accumulator, 16, 16, 16, float> fc[4];
#pragma unroll
        for (int i = 0; i < 4; i++) wmma::fill_fragment(fc[i], 0.f);
#pragma unroll
        for (int ks = 0; ks < 8; ks++) {
            wmma::fragment<wmma::matrix_a, 16, 16, 16, __half, wmma::row_major> fah, fal;
            wmma::load_matrix_sync(fah, sAhi + mrow * 136 + ks * 16, 136);
            wmma::load_matrix_sync(fal, sAlo + mrow * 136 + ks * 16, 136);
#pragma unroll
            for (int ct = 0; ct < 4; ct++) {
                wmma::fragment<wmma::matrix_b, 16, 16, 16, __half, wmma::row_major> fb;
                wmma::load_matrix_sync(fb, sW + (ks * 16) * 136 + ncol + ct * 16, 136);
                wmma::mma_sync(fc[ct], fah, fb, fc[ct]);
                wmma::mma_sync(fc[ct], fal, fb, fc[ct]);
            }
        }
        __syncthreads();   // A reads done
        float* stage = (float*)sAhi;   // 64 x 136 floats
#pragma unroll
        for (int ct = 0; ct < 4; ct++)
            wmma::store_matrix_sync(stage + mrow * 136 + ncol + ct * 16, fc[ct], 136,
                                    wmma::mem_row_major);
        __syncthreads();

        // feat store + fused el/er
        for (int p = tid; p < 1024; p += 256) {
            int row = p >> 4, c8 = (p & 15) * 8;
            int gr = row0 + row;
            const float* s = stage + row * 136 + c8;
            float s0 = s[0], s1 = s[1], s2 = s[2], s3 = s[3];
            float s4 = s[4], s5 = s[5], s6 = s[6], s7 = s[7];
            if (gr < NN) {
                __half2 h0 = __floats2half2_rn(s0, s1);
                __half2 h1 = __floats2half2_rn(s2, s3);
                __half2 h2 = __floats2half2_rn(s4, s5);
                __half2 h3 = __floats2half2_rn(s6, s7);
                uint4 pack;
                pack.x = *(unsigned*)&h0; pack.y = *(unsigned*)&h1;
                pack.z = *(unsigned*)&h2; pack.w = *(unsigned*)&h3;
                *(uint4*)(feat + (size_t)gr * 128 + c8) = pack;
            }
            int h = c8 >> 5;
            const float* al8 = s_al + c8;
            const float* ar8 = s_ar + c8;
            float pl = s0 * al8[0] + s1 * al8[1] + s2 * al8[2] + s3 * al8[3]
                     + s4 * al8[4] + s5 * al8[5] + s6 * al8[6] + s7 * al8[7];
            float pr = s0 * ar8[0] + s1 * ar8[1] + s2 * ar8[2] + s3 * ar8[3]
                     + s4 * ar8[4] + s5 * ar8[5] + s6 * ar8[6] + s7 * ar8[7];
            pl += __shfl_xor_sync(0xffffffffu, pl, 1);
            pl += __shfl_xor_sync(0xffffffffu, pl, 2);
            pr += __shfl_xor_sync(0xffffffffu, pr, 1);
            pr += __shfl_xor_sync(0xffffffffu, pr, 2);
            if ((p & 3) == 0 && gr < NN) {
                el[gr * 4 + h] = pl;
                er[gr * 4 + h] = pr;
            }
        }
    }
}

// ---------------- fused softmax (max-free) + aggregation + BN stats ----------
template <bool RES, bool ACT>
__global__ void k_agg(const __half* __restrict__ feat, const float* __restrict__ hin,
                      const float4* __restrict__ el4, const float4* __restrict__ er4,
                      const float* __restrict__ snorm, const int* __restrict__ rowptr,
                      const int* __restrict__ csr, float* __restrict__ out,
                      float* __restrict__ bnstat, const float* __restrict__ pstat,
                      const float* __restrict__ pgamma, const float* __restrict__ pbeta) {
    __shared__ int   s_sj[8][32];
    __shared__ float s_a[8][32][4];
    __shared__ float bs[1024];
    __shared__ float bq[1024];
    __shared__ float psc[128], psh[128];
    int warp = threadIdx.x >> 5;
    int lane = threadIdx.x & 31;
    int node = blockIdx.x * 8 + warp;   // NN % 8 == 0
    if (RES) {
        int t = threadIdx.x;
        if (t < 128) {
            float mu = pstat[t] * (1.f / NN);
            float var = pstat[128 + t] * (1.f / NN) - mu * mu;
            float r = rsqrtf(var + 1e-5f);
            psc[t] = pgamma[t] * r;
            psh[t] = pbeta[t] - mu * pgamma[t] * r;
        }
        __syncthreads();
    }
    int start = rowptr[node], end = rowptr[node + 1];
    int deg = end - start;
    float4 er = er4[node];
    int hl = lane >> 3;
    int c0 = lane * 4;

    float4 acc = make_float4(0.f, 0.f, 0.f, 0.f);
    if (RES) {
        float4 h = *(const float4*)&hin[(size_t)node * 128 + c0];
        acc.x = eluf(h.x * psc[c0] + psh[c0]);
        acc.y = eluf(h.y * psc[c0 + 1] + psh[c0 + 1]);
        acc.z = eluf(h.z * psc[c0 + 2] + psh[c0 + 2]);
        acc.w = eluf(h.w * psc[c0 + 3] + psh[c0 + 3]);
    }

    if (deg <= 32) {
        bool on = lane < deg;
        int s = on ? csr[start + lane] : 0;
        float4 ex = make_float4(0.f, 0.f, 0.f, 0.f);
        if (on) {
            float4 e = el4[s];
            ex.x = __expf(lrelu(e.x + er.x));
            ex.y = __expf(lrelu(e.y + er.y));
            ex.z = __expf(lrelu(e.z + er.z));
            ex.w = __expf(lrelu(e.w + er.w));
        }
        float4 sm4 = ex;
#pragma unroll
        for (int o = 16; o > 0; o >>= 1) {
            sm4.x += __shfl_xor_sync(0xffffffffu, sm4.x, o);
            sm4.y += __shfl_xor_sync(0xffffffffu, sm4.y, o);
            sm4.z += __shfl_xor_sync(0xffffffffu, sm4.z, o);
            sm4.w += __shfl_xor_sync(0xffffffffu, sm4.w, o);
        }
        s_sj[warp][lane] = s;
        float4 aex = make_float4(ex.x / sm4.x, ex.y / sm4.y, ex.z / sm4.z, ex.w / sm4.w);
        *(float4*)&s_a[warp][lane][0] = aex;
        __syncwarp();
        int j = 0;
        for (; j + 4 <= deg; j += 4) {
            int sj0 = s_sj[warp][j],     sj1 = s_sj[warp][j + 1];
            int sj2 = s_sj[warp][j + 2], sj3 = s_sj[warp][j + 3];
            float a0 = s_a[warp][j][hl],     a1 = s_a[warp][j + 1][hl];
            float a2 = s_a[warp][j + 2][hl], a3 = s_a[warp][j + 3][hl];
            uint2 r0 = *(const uint2*)(feat + (size_t)sj0 * 128 + c0);
            uint2 r1 = *(const uint2*)(feat + (size_t)sj1 * 128 + c0);
            uint2 r2 = *(const uint2*)(feat + (size_t)sj2 * 128 + c0);
            uint2 r3 = *(const uint2*)(feat + (size_t)sj3 * 128 + c0);
            float2 p0 = __half22float2(*(__half2*)&r0.x), q0 = __half22float2(*(__half2*)&r0.y);
            float2 p1 = __half22float2(*(__half2*)&r1.x), q1 = __half22float2(*(__half2*)&r1.y);
            float2 p2 = __half22float2(*(__half2*)&r2.x), q2 = __half22float2(*(__half2*)&r2.y);
            float2 p3 = __half22float2(*(__half2*)&r3.x), q3 = __half22float2(*(__half2*)&r3.y);
            acc.x += p0.x * a0 + p1.x * a1 + p2.x * a2 + p3.x * a3;
            acc.y += p0.y * a0 + p1.y * a1 + p2.y * a2 + p3.y * a3;
            acc.z += q0.x * a0 + q1.x * a1 + q2.x * a2 + q3.x * a3;
            acc.w += q0.y * a0 + q1.y * a1 + q2.y * a2 + q3.y * a3;
        }
        for (; j < deg; j++) {
            int sj = s_sj[warp][j];
            float a = s_a[warp][j][hl];
            uint2 raw = *(const uint2*)(feat + (size_t)sj * 128 + c0);
            float2 f01 = __half22float2(*(__half2*)&raw.x);
            float2 f23 = __half22float2(*(__half2*)&raw.y);
            acc.x += f01.x * a; acc.y += f01.y * a;
            acc.z += f23.x * a; acc.w += f23.y * a;
        }
    } else {
        float s0 = 0.f, s1 = 0.f, s2 = 0.f, s3 = 0.f;
        for (int k = start + lane; k < end; k += 32) {
            int s = csr[k];
            float4 e = el4[s];
            s0 += __expf(lrelu(e.x + er.x));
            s1 += __expf(lrelu(e.y + er.y));
            s2 += __expf(lrelu(e.z + er.z));
            s3 += __expf(lrelu(e.w + er.w));
        }
#pragma unroll
        for (int o = 16; o > 0; o >>= 1) {
            s0 += __shfl_xor_sync(0xffffffffu, s0, o);
            s1 += __shfl_xor_sync(0xffffffffu, s1, o);
            s2 += __shfl_xor_sync(0xffffffffu, s2, o);
            s3 += __shfl_xor_sync(0xffffffffu, s3, o);
        }
        float invh = 1.f / (hl == 0 ? s0 : hl == 1 ? s1 : hl == 2 ? s2 : s3);
        float erh = hl == 0 ? er.x : hl == 1 ? er.y : hl == 2 ? er.z : er.w;
        int k = start;
        for (; k + 4 <= end; k += 4) {
            int sj0 = csr[k], sj1 = csr[k + 1], sj2 = csr[k + 2], sj3 = csr[k + 3];
            float4 e0 = el4[sj0], e1 = el4[sj1], e2 = el4[sj2], e3 = el4[sj3];
            float ev0 = hl == 0 ? e0.x : hl == 1 ? e0.y : hl == 2 ? e0.z : e0.w;
            float ev1 = hl == 0 ? e1.x : hl == 1 ? e1.y : hl == 2 ? e1.z : e1.w;
            float ev2 = hl == 0 ? e2.x : hl == 1 ? e2.y : hl == 2 ? e2.z : e2.w;
            float ev3 = hl == 0 ? e3.x : hl == 1 ? e3.y : hl == 2 ? e3.z : e3.w;
            float a0 = __expf(lrelu(ev0 + erh)) * invh;
            float a1 = __expf(lrelu(ev1 + erh)) * invh;
            float a2 = __expf(lrelu(ev2 + erh)) * invh;
            float a3 = __expf(lrelu(ev3 + erh)) * invh;
            uint2 r0 = *(const uint2*)(feat + (size_t)sj0 * 128 + c0);
            uint2 r1 = *(const uint2*)(feat + (size_t)sj1 * 128 + c0);
            uint2 r2 = *(const uint2*)(feat + (size_t)sj2 * 128 + c0);
            uint2 r3 = *(const uint2*)(feat + (size_t)sj3 * 128 + c0);
            float2 p0 = __half22float2(*(__half2*)&r0.x), q0 = __half22float2(*(__half2*)&r0.y);
            float2 p1 = __half22float2(*(__half2*)&r1.x), q1 = __half22float2(*(__half2*)&r1.y);
            float2 p2 = __half22float2(*(__half2*)&r2.x), q2 = __half22float2(*(__half2*)&r2.y);
            float2 p3 = __half22float2(*(__half2*)&r3.x), q3 = __half22float2(*(__half2*)&r3.y);
            acc.x += p0.x * a0 + p1.x * a1 + p2.x * a2 + p3.x * a3;
            acc.y += p0.y * a0 + p1.y * a1 + p2.y * a2 + p3.y * a3;
            acc.z += q0.x * a0 + q1.x * a1 + q2.x * a2 + q3.x * a3;
            acc.w += q0.y * a0 + q1.y * a1 + q2.y * a2 + q3.y * a3;
        }
        for (; k < end; k++) {
            int s = csr[k];
            float4 e = el4[s];
            float ev = hl == 0 ? e.x : hl == 1 ? e.y : hl == 2 ? e.z : e.w;
            float a = __expf(lrelu(ev + erh)) * invh;
            uint2 raw = *(const uint2*)(feat + (size_t)s * 128 + c0);
            float2 f01 = __half22float2(*(__half2*)&raw.x);
            float2 f23 = __half22float2(*(__half2*)&raw.y);
            acc.x += f01.x * a; acc.y += f01.y * a;
            acc.z += f23.x * a; acc.w += f23.y * a;
        }
    }
    if (ACT) {
        acc.x = eluf(acc.x); acc.y = eluf(acc.y);
        acc.z = eluf(acc.z); acc.w = eluf(acc.w);
    }
    float sn = snorm[node];
    acc.x *= sn; acc.y *= sn; acc.z *= sn; acc.w *= sn;
    *(float4*)&out[(size_t)node * 128 + c0] = acc;

    ((float4*)bs)[warp * 32 + lane] = acc;
    ((float4*)bq)[warp * 32 + lane] =
        make_float4(acc.x * acc.x, acc.y * acc.y, acc.z * acc.z, acc.w * acc.w);
    __syncthreads();
    int t = threadIdx.x;
    if (t < 128) {
        float s = 0.f, q = 0.f;
#pragma unroll
        for (int w = 0; w < 8; w++) { s += bs[w * 128 + t]; q += bq[w * 128 + t]; }
        atomicAdd(&bnstat[t], s);
        atomicAdd(&bnstat[128 + t], q);
    }
}

// ---------------- classifier: HMMA 128->64 (A split, W fp16), then 64->2 -----
__global__ void k_cls(const float* __restrict__ H, const float* __restrict__ w1,
                      const float* __restrict__ b1, const float* __restrict__ w2,
                      const float* __restrict__ b2, const float* __restrict__ stat,
                      const float* __restrict__ gamma, const float* __restrict__ beta,
                      float* __restrict__ out) {
    extern __shared__ __half smh[];
    __half* sW   = smh;                  // 128 x 72
    __half* sAhi = sW + 128 * 72;        // 64 x 136
    __half* sAlo = sAhi + 64 * 136;      // 64 x 136
    __shared__ float sc[128], shf[128];
    int tid = threadIdx.x, warp = tid >> 5;
    int row0 = blockIdx.x * 64;
    if (tid < 128) {
        float mu = stat[tid] * (1.f / NN);
        float var = stat[128 + tid] * (1.f / NN) - mu * mu;
        float r = rsqrtf(var + 1e-5f);
        sc[tid] = gamma[tid] * r;
        shf[tid] = beta[tid] - mu * gamma[tid] * r;
    }
    __syncthreads();

    for (int p = tid; p < 2048; p += 256) {
        int r = p >> 4, c = (p & 15) * 4;
        float4 v = *(const float4*)&w1[(size_t)r * 64 + c];
        sW[r * 72 + c]     = __float2half_rn(v.x);
        sW[r * 72 + c + 1] = __float2half_rn(v.y);
        sW[r * 72 + c + 2] = __float2half_rn(v.z);
        sW[r * 72 + c + 3] = __float2half_rn(v.w);
    }
    for (int p = tid; p < 2048; p += 256) {
        int row = p >> 5, c = (p & 31) * 4;
        int gr = row0 + row;
        float4 v = make_float4(0.f, 0.f, 0.f, 0.f);
        if (gr < NN) {
            v = *(const float4*)&H[(size_t)gr * 128 + c];
            v.x = eluf(v.x * sc[c] + shf[c]);
            v.y = eluf(v.y * sc[c + 1] + shf[c + 1]);
            v.z = eluf(v.z * sc[c + 2] + shf[c + 2]);
            v.w = eluf(v.w * sc[c + 3] + shf[c + 3]);
        }
        split2h(v.x, sAhi[row * 136 + c], sAlo[row * 136 + c]);
        split2h(v.y, sAhi[row * 136 + c + 1], sAlo[row * 136 + c + 1]);
        split2h(v.z, sAhi[row * 136 + c + 2], sAlo[row * 136 + c + 2]);
        split2h(v.w, sAhi[row * 136 + c + 3], sAlo[row * 136 + c + 3]);
    }
    __syncthreads();

    int mrow = (warp & 3) * 16;
    int ncol = (warp >> 2) * 32;
    wmma::fragment<wmma::accumulator, 16, 16, 16, float> fc[2];
#pragma unroll
    for (int i = 0; i < 2; i++) wmma::fill_fragment(fc[i], 0.f);
#pragma unroll
    for (int ks = 0; ks < 8; ks++) {
        wmma::fragment<wmma::matrix_a, 16, 16, 16, __half, wmma::row_major> fah, fal;
        wmma::load_matrix_sync(fah, sAhi + mrow * 136 + ks * 16, 136);
        wmma::load_matrix_sync(fal, sAlo + mrow * 136 + ks * 16, 136);
#pragma unroll
        for (int ct = 0; ct < 2; ct++) {
            wmma::fragment<wmma::matrix_b, 16, 16, 16, __half, wmma::row_major> fb;
            wmma::load_matrix_sync(fb, sW + (ks * 16) * 72 + ncol + ct * 16, 72);
            wmma::mma_sync(fc[ct], fah, fb, fc[ct]);
            wmma::mma_sync(fc[ct], fal, fb, fc[ct]);
        }
    }
    __syncthreads();
    float* stage = (float*)sAhi;  // 64 x 72
#pragma unroll
    for (int ct = 0; ct < 2; ct++)
        wmma::store_matrix_sync(stage + mrow * 72 + ncol + ct * 16, fc[ct], 72,
                                wmma::mem_row_major);
    __syncthreads();
    if (tid < 128) {
        int row = tid >> 1, o = tid & 1;
        int gr = row0 + row;
        if (gr < NN) {
            float s = b2[o];
            for (int k = 0; k < 64; k++) {
                float hv = stage[row * 72 + k] + b1[k];
                hv = hv > 0.f ? hv : 0.f;
                s += hv * w2[k * 2 + o];
            }
            out[(size_t)gr * 2 + o] = s;
        }
    }
}

// ---------------- host orchestration -----------------------------------------
extern "C" void kernel_launch(void* const* d_in, const int* in_sizes, int n_in,
                              void* d_out, int out_size) {
    const int* x = (const int*)d_in[0];
    const int* src = (const int*)d_in[1];
    const int* dst = (const int*)d_in[2];
    const float* snorm_n = (const float*)d_in[3];
    const float* embed = (const float*)d_in[5];
    const float* W[3] = {(const float*)d_in[6], (const float*)d_in[11], (const float*)d_in[16]};
    const float* al[3] = {(const float*)d_in[7], (const float*)d_in[12], (const float*)d_in[17]};
    const float* ar[3] = {(const float*)d_in[8], (const float*)d_in[13], (const float*)d_in[18]};
    const float* gamma[3] = {(const float*)d_in[9], (const float*)d_in[14], (const float*)d_in[19]};
    const float* beta[3] = {(const float*)d_in[10], (const float*)d_in[15], (const float*)d_in[20]};
    const float* cls1_w = (const float*)d_in[21];
    const float* cls1_b = (const float*)d_in[22];
    const float* cls2_w = (const float*)d_in[23];
    const float* cls2_b = (const float*)d_in[24];
    float* out = (float*)d_out;

    float *h0, *h1, *el, *er, *bnstat;
    __half* feath;
    int *deg, *rowptr, *cursor, *csr;
    cudaGetSymbolAddress((void**)&h0, g_h0);
    cudaGetSymbolAddress((void**)&h1, g_h1);
    cudaGetSymbolAddress((void**)&feath, g_feath);
    cudaGetSymbolAddress((void**)&el, g_el);
    cudaGetSymbolAddress((void**)&er, g_er);
    cudaGetSymbolAddress((void**)&bnstat, g_bnstat);
    cudaGetSymbolAddress((void**)&deg, g_deg);
    cudaGetSymbolAddress((void**)&rowptr, g_rowptr);
    cudaGetSymbolAddress((void**)&cursor, g_cursor);
    cudaGetSymbolAddress((void**)&csr, g_csr);

    const int GEMM_SMEM = (128 * 136 + 2 * 64 * 136) * 2;  // 69632
    const int CLS_SMEM  = (128 * 72 + 2 * 64 * 136) * 2;   // 53248
    static bool attr_done = false;
    static cudaStream_t s2 = nullptr;
    static cudaEvent_t evFork = nullptr, evJoin = nullptr;
    if (!attr_done) {
        cudaFuncSetAttribute(k_gemm<true>, cudaFuncAttributeMaxDynamicSharedMemorySize, GEMM_SMEM);
        cudaFuncSetAttribute(k_gemm<false>, cudaFuncAttributeMaxDynamicSharedMemorySize, GEMM_SMEM);
        cudaFuncSetAttribute(k_cls, cudaFuncAttributeMaxDynamicSharedMemorySize, CLS_SMEM);
        cudaStreamCreateWithFlags(&s2, cudaStreamNonBlocking);
        cudaEventCreateWithFlags(&evFork, cudaEventDisableTiming);
        cudaEventCreateWithFlags(&evJoin, cudaEventDisableTiming);
        attr_done = true;
    }

    // Fork: CSR build + bnstat clear on side stream, overlapped with gemm0.
    cudaEventRecord(evFork, 0);
    cudaStreamWaitEvent(s2, evFork, 0);
    cudaMemsetAsync(deg, 0, NN * sizeof(int), s2);
    cudaMemsetAsync(bnstat, 0, 3 * 256 * sizeof(float), s2);
    k_hist<<<(EE + 255) / 256, 256, 0, s2>>>(dst, deg);
    k_scan_all<<<1, 1024, 0, s2>>>(deg, rowptr, cursor);
    k_fill<<<(EE + 255) / 256, 256, 0, s2>>>(src, dst, cursor, csr);
    cudaEventRecord(evJoin, s2);

    // Main stream: layer-0 GEMM (independent of CSR).
    k_gemm<true><<<PGRID, 256, GEMM_SMEM>>>(nullptr, x, embed, W[0],
                                            nullptr, nullptr, nullptr,
                                            al[0], ar[0], feath, el, er);
    cudaStreamWaitEvent(0, evJoin, 0);

    k_agg<false, false><<<NN / 8, 256>>>(feath, nullptr, (const float4*)el,
                                         (const float4*)er, snorm_n, rowptr, csr,
                                         h0, &bnstat[0], nullptr, nullptr, nullptr);
    // layer 1
    k_gemm<false><<<PGRID, 256, GEMM_SMEM>>>(h0, nullptr, nullptr, W[1],
                                             &bnstat[0], gamma[0], beta[0],
                                             al[1], ar[1], feath, el, er);
    k_agg<true, true><<<NN / 8, 256>>>(feath, h0, (const float4*)el,
                                       (const float4*)er, snorm_n, rowptr, csr,
                                       h1, &bnstat[256], &bnstat[0], gamma[0], beta[0]);
    // layer 2
    k_gemm<false><<<PGRID, 256, GEMM_SMEM>>>(h1, nullptr, nullptr, W[2],
                                             &bnstat[256], gamma[1], beta[1],
                                             al[2], ar[2], feath, el, er);
    k_agg<true, true><<<NN / 8, 256>>>(feath, h1, (const float4*)el,
                                       (const float4*)er, snorm_n, rowptr, csr,
                                       h0, &bnstat[512], &bnstat[256], gamma[1], beta[1]);
    // classifier
    k_cls<<<(NN + 63) / 64, 256, CLS_SMEM>>>(h0, cls1_w, cls1_b, cls2_w, cls2_b,
                                             &bnstat[512], gamma[2], beta[2], out);
}

// round 14
// speedup vs baseline: 1.1098x; 1.1098x over previous
#include <cuda_runtime.h>
#include <cuda_fp16.h>
#include <mma.h>
using namespace nvcuda;

#define NN 50000
#define EE 850000
#define NTILES 782   // ceil(NN/64)
#define PGRID 444

// ---------------- scratch (device globals) ----------------------------------
__device__ float  g_h0[NN * 128];
__device__ float  g_h1[NN * 128];
__device__ __half g_feath[NN * 128];
__device__ float  g_el[NN * 4];
__device__ float  g_er[NN * 4];
__device__ int    g_deg[NN];
__device__ int    g_rowptr[NN + 1];
__device__ int    g_cursor[NN];
__device__ int    g_csr[EE];
__device__ int    g_partial[256];
__device__ int    g_poff[256];
__device__ float  g_bnstat[3 * 256];

__device__ __forceinline__ float eluf(float x) { return x > 0.f ? x : (__expf(x) - 1.f); }
__device__ __forceinline__ float lrelu(float x) { return x > 0.f ? x : 0.2f * x; }

__device__ __forceinline__ void split2h(float v, __half& hi, __half& lo) {
    hi = __float2half_rn(v);
    lo = __float2half_rn(v - __half2float(hi));
}

// ---------------- CSR build --------------------------------------------------
__global__ void k_hist(const int* __restrict__ dst, int* deg) {
    int i = blockIdx.x * blockDim.x + threadIdx.x;
    if (i < EE) atomicAdd(&deg[dst[i]], 1);
}

__device__ __forceinline__ int block_scan_excl(int v, int t) {
    __shared__ int ws[8];
    int lane = t & 31, w = t >> 5;
    int incl = v;
#pragma unroll
    for (int o = 1; o < 32; o <<= 1) {
        int u = __shfl_up_sync(0xffffffffu, incl, o);
        if (lane >= o) incl += u;
    }
    if (lane == 31) ws[w] = incl;
    __syncthreads();
    if (t == 0) {
        int run = 0;
#pragma unroll
        for (int i = 0; i < 8; i++) { int x = ws[i]; ws[i] = run; run += x; }
    }
    __syncthreads();
    return incl - v + ws[w];
}

__global__ void k_scan1(const int* __restrict__ deg, int* __restrict__ partial) {
    __shared__ int ws[8];
    int t = threadIdx.x, idx = blockIdx.x * 256 + t;
    int v = (idx < NN) ? deg[idx] : 0;
#pragma unroll
    for (int o = 16; o > 0; o >>= 1) v += __shfl_xor_sync(0xffffffffu, v, o);
    if ((t & 31) == 0) ws[t >> 5] = v;
    __syncthreads();
    if (t == 0) {
        int s = 0;
#pragma unroll
        for (int i = 0; i < 8; i++) s += ws[i];
        partial[blockIdx.x] = s;
    }
}

__global__ void k_scan2(const int* __restrict__ partial, int* __restrict__ poff, int nblk) {
    int t = threadIdx.x;
    int v = (t < nblk) ? partial[t] : 0;
    int excl = block_scan_excl(v, t);
    if (t < nblk) poff[t] = excl;
}

__global__ void k_scan3(const int* __restrict__ deg, const int* __restrict__ poff,
                        int* __restrict__ rowptr, int* __restrict__ cursor) {
    int t = threadIdx.x, idx = blockIdx.x * 256 + t;
    int v = (idx < NN) ? deg[idx] : 0;
    int excl = block_scan_excl(v, t);
    int res = poff[blockIdx.x] + excl;
    if (idx <= NN) rowptr[idx] = res;
    if (idx < NN) cursor[idx] = res;
}

__global__ void k_fill(const int* __restrict__ src, const int* __restrict__ dst,
                       int* cursor, int* __restrict__ csr) {
    int i = blockIdx.x * blockDim.x + threadIdx.x;
    if (i < EE) {
        int d = dst[i];
        int pos = atomicAdd(&cursor[d], 1);
        csr[pos] = src[i];
    }
}

// ---------------- persistent HMMA GEMM (64-row tiles) + fused el/er ----------
template <bool L0>
__global__ void k_gemm(const float* __restrict__ A, const int* __restrict__ xidx,
                       const float* __restrict__ embed, const float* __restrict__ W,
                       const float* __restrict__ stat, const float* __restrict__ gamma,
                       const float* __restrict__ beta, const float* __restrict__ alv,
                       const float* __restrict__ arv, __half* __restrict__ feat,
                       float* __restrict__ el, float* __restrict__ er) {
    extern __shared__ __half smh[];
    __half* sW   = smh;                    // 128 x 136
    __half* sAhi = sW + 128 * 136;         // 64 x 136
    __half* sAlo = sAhi + 64 * 136;        // 64 x 136
    __shared__ float sc[128], shf[128];
    __shared__ float s_al[128], s_ar[128];
    int tid = threadIdx.x, warp = tid >> 5;

    if (!L0) {
        if (tid < 128) {
            float mu = stat[tid] * (1.f / NN);
            float var = stat[128 + tid] * (1.f / NN) - mu * mu;
            float r = rsqrtf(var + 1e-5f);
            sc[tid] = gamma[tid] * r;
            shf[tid] = beta[tid] - mu * gamma[tid] * r;
        }
    }
    if (tid < 128) { s_al[tid] = alv[tid]; s_ar[tid] = arv[tid]; }

    for (int p = tid; p < 4096; p += 256) {
        int r = p >> 5, c = (p & 31) * 4;
        float4 v = *(const float4*)&W[(size_t)r * 128 + c];
        sW[r * 136 + c]     = __float2half_rn(v.x);
        sW[r * 136 + c + 1] = __float2half_rn(v.y);
        sW[r * 136 + c + 2] = __float2half_rn(v.z);
        sW[r * 136 + c + 3] = __float2half_rn(v.w);
    }

    int mrow = (warp & 3) * 16;
    int ncol = (warp >> 2) * 64;

    for (int tile = blockIdx.x; tile < NTILES; tile += gridDim.x) {
        int row0 = tile * 64;
        __syncthreads();   // W ready / stage consumed
        for (int p = tid; p < 2048; p += 256) {
            int row = p >> 5, c = (p & 31) * 4;
            int gr = row0 + row;
            float4 v = make_float4(0.f, 0.f, 0.f, 0.f);
            if (gr < NN) {
                if (L0) v = *(const float4*)&embed[(size_t)xidx[gr] * 128 + c];
                else {
                    v = *(const float4*)&A[(size_t)gr * 128 + c];
                    v.x = eluf(v.x * sc[c] + shf[c]);
                    v.y = eluf(v.y * sc[c + 1] + shf[c + 1]);
                    v.z = eluf(v.z * sc[c + 2] + shf[c + 2]);
                    v.w = eluf(v.w * sc[c + 3] + shf[c + 3]);
                }
            }
            split2h(v.x, sAhi[row * 136 + c], sAlo[row * 136 + c]);
            split2h(v.y, sAhi[row * 136 + c + 1], sAlo[row * 136 + c + 1]);
            split2h(v.z, sAhi[row * 136 + c + 2], sAlo[row * 136 + c + 2]);
            split2h(v.w, sAhi[row * 136 + c + 3], sAlo[row * 136 + c + 3]);
        }
        __syncthreads();

        wmma::fragment<wmma::accumulator, 16, 16, 16, float> fc[4];
#pragma unroll
        for (int i = 0; i < 4; i++) wmma::fill_fragment(fc[i], 0.f);
#pragma unroll
        for (int ks = 0; ks < 8; ks++) {
            wmma::fragment<wmma::matrix_a, 16, 16, 16, __half, wmma::row_major> fah, fal;
            wmma::load_matrix_sync(fah, sAhi + mrow * 136 + ks * 16, 136);
            wmma::load_matrix_sync(fal, sAlo + mrow * 136 + ks * 16, 136);
#pragma unroll
            for (int ct = 0; ct < 4; ct++) {
                wmma::fragment<wmma::matrix_b, 16, 16, 16, __half, wmma::row_major> fb;
                wmma::load_matrix_sync(fb, sW + (ks * 16) * 136 + ncol + ct * 16, 136);
                wmma::mma_sync(fc[ct], fah, fb, fc[ct]);
                wmma::mma_sync(fc[ct], fal, fb, fc[ct]);
            }
        }
        __syncthreads();   // A reads done
        float* stage = (float*)sAhi;   // 64 x 136 floats
#pragma unroll
        for (int ct = 0; ct < 4; ct++)
            wmma::store_matrix_sync(stage + mrow * 136 + ncol + ct * 16, fc[ct], 136,
                                    wmma::mem_row_major);
        __syncthreads();

        // feat store + fused el/er
        for (int p = tid; p < 1024; p += 256) {
            int row = p >> 4, c8 = (p & 15) * 8;
            int gr = row0 + row;
            const float* s = stage + row * 136 + c8;
            float s0 = s[0], s1 = s[1], s2 = s[2], s3 = s[3];
            float s4 = s[4], s5 = s[5], s6 = s[6], s7 = s[7];
            if (gr < NN) {
                __half2 h0 = __floats2half2_rn(s0, s1);
                __half2 h1 = __floats2half2_rn(s2, s3);
                __half2 h2 = __floats2half2_rn(s4, s5);
                __half2 h3 = __floats2half2_rn(s6, s7);
                uint4 pack;
                pack.x = *(unsigned*)&h0; pack.y = *(unsigned*)&h1;
                pack.z = *(unsigned*)&h2; pack.w = *(unsigned*)&h3;
                *(uint4*)(feat + (size_t)gr * 128 + c8) = pack;
            }
            int h = c8 >> 5;
            const float* al8 = s_al + c8;
            const float* ar8 = s_ar + c8;
            float pl = s0 * al8[0] + s1 * al8[1] + s2 * al8[2] + s3 * al8[3]
                     + s4 * al8[4] + s5 * al8[5] + s6 * al8[6] + s7 * al8[7];
            float pr = s0 * ar8[0] + s1 * ar8[1] + s2 * ar8[2] + s3 * ar8[3]
                     + s4 * ar8[4] + s5 * ar8[5] + s6 * ar8[6] + s7 * ar8[7];
            pl += __shfl_xor_sync(0xffffffffu, pl, 1);
            pl += __shfl_xor_sync(0xffffffffu, pl, 2);
            pr += __shfl_xor_sync(0xffffffffu, pr, 1);
            pr += __shfl_xor_sync(0xffffffffu, pr, 2);
            if ((p & 3) == 0 && gr < NN) {
                el[gr * 4 + h] = pl;
                er[gr * 4 + h] = pr;
            }
        }
    }
}

// ---------------- fused softmax (max-free) + aggregation + BN stats ----------
template <bool RES, bool ACT>
__global__ void k_agg(const __half* __restrict__ feat, const float* __restrict__ hin,
                      const float4* __restrict__ el4, const float4* __restrict__ er4,
                      const float* __restrict__ snorm, const int* __restrict__ rowptr,
                      const int* __restrict__ csr, float* __restrict__ out,
                      float* __restrict__ bnstat, const float* __restrict__ pstat,
                      const float* __restrict__ pgamma, const float* __restrict__ pbeta) {
    __shared__ int   s_sj[8][32];
    __shared__ float s_a[8][32][4];
    __shared__ float bs[1024];
    __shared__ float bq[1024];
    __shared__ float psc[128], psh[128];
    int warp = threadIdx.x >> 5;
    int lane = threadIdx.x & 31;
    int node = blockIdx.x * 8 + warp;   // NN % 8 == 0
    if (RES) {
        int t = threadIdx.x;
        if (t < 128) {
            float mu = pstat[t] * (1.f / NN);
            float var = pstat[128 + t] * (1.f / NN) - mu * mu;
            float r = rsqrtf(var + 1e-5f);
            psc[t] = pgamma[t] * r;
            psh[t] = pbeta[t] - mu * pgamma[t] * r;
        }
        __syncthreads();
    }
    int start = rowptr[node], end = rowptr[node + 1];
    int deg = end - start;
    float4 er = er4[node];
    int hl = lane >> 3;
    int c0 = lane * 4;

    float4 acc = make_float4(0.f, 0.f, 0.f, 0.f);
    if (RES) {
        float4 h = *(const float4*)&hin[(size_t)node * 128 + c0];
        acc.x = eluf(h.x * psc[c0] + psh[c0]);
        acc.y = eluf(h.y * psc[c0 + 1] + psh[c0 + 1]);
        acc.z = eluf(h.z * psc[c0 + 2] + psh[c0 + 2]);
        acc.w = eluf(h.w * psc[c0 + 3] + psh[c0 + 3]);
    }

    if (deg <= 32) {
        bool on = lane < deg;
        int s = on ? csr[start + lane] : 0;
        float4 ex = make_float4(0.f, 0.f, 0.f, 0.f);
        if (on) {
            float4 e = el4[s];
            ex.x = __expf(lrelu(e.x + er.x));
            ex.y = __expf(lrelu(e.y + er.y));
            ex.z = __expf(lrelu(e.z + er.z));
            ex.w = __expf(lrelu(e.w + er.w));
        }
        float4 sm4 = ex;
#pragma unroll
        for (int o = 16; o > 0; o >>= 1) {
            sm4.x += __shfl_xor_sync(0xffffffffu, sm4.x, o);
            sm4.y += __shfl_xor_sync(0xffffffffu, sm4.y, o);
            sm4.z += __shfl_xor_sync(0xffffffffu, sm4.z, o);
            sm4.w += __shfl_xor_sync(0xffffffffu, sm4.w, o);
        }
        s_sj[warp][lane] = s;
        float4 aex = make_float4(ex.x / sm4.x, ex.y / sm4.y, ex.z / sm4.z, ex.w / sm4.w);
        *(float4*)&s_a[warp][lane][0] = aex;
        __syncwarp();
        int j = 0;
        for (; j + 4 <= deg; j += 4) {
            int sj0 = s_sj[warp][j],     sj1 = s_sj[warp][j + 1];
            int sj2 = s_sj[warp][j + 2], sj3 = s_sj[warp][j + 3];
            float a0 = s_a[warp][j][hl],     a1 = s_a[warp][j + 1][hl];
            float a2 = s_a[warp][j + 2][hl], a3 = s_a[warp][j + 3][hl];
            uint2 r0 = *(const uint2*)(feat + (size_t)sj0 * 128 + c0);
            uint2 r1 = *(const uint2*)(feat + (size_t)sj1 * 128 + c0);
            uint2 r2 = *(const uint2*)(feat + (size_t)sj2 * 128 + c0);
            uint2 r3 = *(const uint2*)(feat + (size_t)sj3 * 128 + c0);
            float2 p0 = __half22float2(*(__half2*)&r0.x), q0 = __half22float2(*(__half2*)&r0.y);
            float2 p1 = __half22float2(*(__half2*)&r1.x), q1 = __half22float2(*(__half2*)&r1.y);
            float2 p2 = __half22float2(*(__half2*)&r2.x), q2 = __half22float2(*(__half2*)&r2.y);
            float2 p3 = __half22float2(*(__half2*)&r3.x), q3 = __half22float2(*(__half2*)&r3.y);
            acc.x += p0.x * a0 + p1.x * a1 + p2.x * a2 + p3.x * a3;
            acc.y += p0.y * a0 + p1.y * a1 + p2.y * a2 + p3.y * a3;
            acc.z += q0.x * a0 + q1.x * a1 + q2.x * a2 + q3.x * a3;
            acc.w += q0.y * a0 + q1.y * a1 + q2.y * a2 + q3.y * a3;
        }
        for (; j < deg; j++) {
            int sj = s_sj[warp][j];
            float a = s_a[warp][j][hl];
            uint2 raw = *(const uint2*)(feat + (size_t)sj * 128 + c0);
            float2 f01 = __half22float2(*(__half2*)&raw.x);
            float2 f23 = __half22float2(*(__half2*)&raw.y);
            acc.x += f01.x * a; acc.y += f01.y * a;
            acc.z += f23.x * a; acc.w += f23.y * a;
        }
    } else {
        float s0 = 0.f, s1 = 0.f, s2 = 0.f, s3 = 0.f;
        for (int k = start + lane; k < end; k += 32) {
            int s = csr[k];
            float4 e = el4[s];
            s0 += __expf(lrelu(e.x + er.x));
            s1 += __expf(lrelu(e.y + er.y));
            s2 += __expf(lrelu(e.z + er.z));
            s3 += __expf(lrelu(e.w + er.w));
        }
#pragma unroll
        for (int o = 16; o > 0; o >>= 1) {
            s0 += __shfl_xor_sync(0xffffffffu, s0, o);
            s1 += __shfl_xor_sync(0xffffffffu, s1, o);
            s2 += __shfl_xor_sync(0xffffffffu, s2, o);
            s3 += __shfl_xor_sync(0xffffffffu, s3, o);
        }
        float invh = 1.f / (hl == 0 ? s0 : hl == 1 ? s1 : hl == 2 ? s2 : s3);
        float erh = hl == 0 ? er.x : hl == 1 ? er.y : hl == 2 ? er.z : er.w;
        int k = start;
        for (; k + 4 <= end; k += 4) {
            int sj0 = csr[k], sj1 = csr[k + 1], sj2 = csr[k + 2], sj3 = csr[k + 3];
            float4 e0 = el4[sj0], e1 = el4[sj1], e2 = el4[sj2], e3 = el4[sj3];
            float ev0 = hl == 0 ? e0.x : hl == 1 ? e0.y : hl == 2 ? e0.z : e0.w;
            float ev1 = hl == 0 ? e1.x : hl == 1 ? e1.y : hl == 2 ? e1.z : e1.w;
            float ev2 = hl == 0 ? e2.x : hl == 1 ? e2.y : hl == 2 ? e2.z : e2.w;
            float ev3 = hl == 0 ? e3.x : hl == 1 ? e3.y : hl == 2 ? e3.z : e3.w;
            float a0 = __expf(lrelu(ev0 + erh)) * invh;
            float a1 = __expf(lrelu(ev1 + erh)) * invh;
            float a2 = __expf(lrelu(ev2 + erh)) * invh;
            float a3 = __expf(lrelu(ev3 + erh)) * invh;
            uint2 r0 = *(const uint2*)(feat + (size_t)sj0 * 128 + c0);
            uint2 r1 = *(const uint2*)(feat + (size_t)sj1 * 128 + c0);
            uint2 r2 = *(const uint2*)(feat + (size_t)sj2 * 128 + c0);
            uint2 r3 = *(const uint2*)(feat + (size_t)sj3 * 128 + c0);
            float2 p0 = __half22float2(*(__half2*)&r0.x), q0 = __half22float2(*(__half2*)&r0.y);
            float2 p1 = __half22float2(*(__half2*)&r1.x), q1 = __half22float2(*(__half2*)&r1.y);
            float2 p2 = __half22float2(*(__half2*)&r2.x), q2 = __half22float2(*(__half2*)&r2.y);
            float2 p3 = __half22float2(*(__half2*)&r3.x), q3 = __half22float2(*(__half2*)&r3.y);
            acc.x += p0.x * a0 + p1.x * a1 + p2.x * a2 + p3.x * a3;
            acc.y += p0.y * a0 + p1.y * a1 + p2.y * a2 + p3.y * a3;
            acc.z += q0.x * a0 + q1.x * a1 + q2.x * a2 + q3.x * a3;
            acc.w += q0.y * a0 + q1.y * a1 + q2.y * a2 + q3.y * a3;
        }
        for (; k < end; k++) {
            int s = csr[k];
            float4 e = el4[s];
            float ev = hl == 0 ? e.x : hl == 1 ? e.y : hl == 2 ? e.z : e.w;
            float a = __expf(lrelu(ev + erh)) * invh;
            uint2 raw = *(const uint2*)(feat + (size_t)s * 128 + c0);
            float2 f01 = __half22float2(*(__half2*)&raw.x);
            float2 f23 = __half22float2(*(__half2*)&raw.y);
            acc.x += f01.x * a; acc.y += f01.y * a;
            acc.z += f23.x * a; acc.w += f23.y * a;
        }
    }
    if (ACT) {
        acc.x = eluf(acc.x); acc.y = eluf(acc.y);
        acc.z = eluf(acc.z); acc.w = eluf(acc.w);
    }
    float sn = snorm[node];
    acc.x *= sn; acc.y *= sn; acc.z *= sn; acc.w *= sn;
    *(float4*)&out[(size_t)node * 128 + c0] = acc;

    ((float4*)bs)[warp * 32 + lane] = acc;
    ((float4*)bq)[warp * 32 + lane] =
        make_float4(acc.x * acc.x, acc.y * acc.y, acc.z * acc.z, acc.w * acc.w);
    __syncthreads();
    int t = threadIdx.x;
    if (t < 128) {
        float s = 0.f, q = 0.f;
#pragma unroll
        for (int w = 0; w < 8; w++) { s += bs[w * 128 + t]; q += bq[w * 128 + t]; }
        atomicAdd(&bnstat[t], s);
        atomicAdd(&bnstat[128 + t], q);
    }
}

// ---------------- classifier: HMMA 128->64 (A split, W fp16), then 64->2 -----
__global__ void k_cls(const float* __restrict__ H, const float* __restrict__ w1,
                      const float* __restrict__ b1, const float* __restrict__ w2,
                      const float* __restrict__ b2, const float* __restrict__ stat,
                      const float* __restrict__ gamma, const float* __restrict__ beta,
                      float* __restrict__ out) {
    extern __shared__ __half smh[];
    __half* sW   = smh;                  // 128 x 72
    __half* sAhi = sW + 128 * 72;        // 64 x 136
    __half* sAlo = sAhi + 64 * 136;      // 64 x 136
    __shared__ float sc[128], shf[128];
    int tid = threadIdx.x, warp = tid >> 5;
    int row0 = blockIdx.x * 64;
    if (tid < 128) {
        float mu = stat[tid] * (1.f / NN);
        float var = stat[128 + tid] * (1.f / NN) - mu * mu;
        float r = rsqrtf(var + 1e-5f);
        sc[tid] = gamma[tid] * r;
        shf[tid] = beta[tid] - mu * gamma[tid] * r;
    }
    __syncthreads();

    for (int p = tid; p < 2048; p += 256) {
        int r = p >> 4, c = (p & 15) * 4;
        float4 v = *(const float4*)&w1[(size_t)r * 64 + c];
        sW[r * 72 + c]     = __float2half_rn(v.x);
        sW[r * 72 + c + 1] = __float2half_rn(v.y);
        sW[r * 72 + c + 2] = __float2half_rn(v.z);
        sW[r * 72 + c + 3] = __float2half_rn(v.w);
    }
    for (int p = tid; p < 2048; p += 256) {
        int row = p >> 5, c = (p & 31) * 4;
        int gr = row0 + row;
        float4 v = make_float4(0.f, 0.f, 0.f, 0.f);
        if (gr < NN) {
            v = *(const float4*)&H[(size_t)gr * 128 + c];
            v.x = eluf(v.x * sc[c] + shf[c]);
            v.y = eluf(v.y * sc[c + 1] + shf[c + 1]);
            v.z = eluf(v.z * sc[c + 2] + shf[c + 2]);
            v.w = eluf(v.w * sc[c + 3] + shf[c + 3]);
        }
        split2h(v.x, sAhi[row * 136 + c], sAlo[row * 136 + c]);
        split2h(v.y, sAhi[row * 136 + c + 1], sAlo[row * 136 + c + 1]);
        split2h(v.z, sAhi[row * 136 + c + 2], sAlo[row * 136 + c + 2]);
        split2h(v.w, sAhi[row * 136 + c + 3], sAlo[row * 136 + c + 3]);
    }
    __syncthreads();

    int mrow = (warp & 3) * 16;
    int ncol = (warp >> 2) * 32;
    wmma::fragment<wmma::accumulator, 16, 16, 16, float> fc[2];
#pragma unroll
    for (int i = 0; i < 2; i++) wmma::fill_fragment(fc[i], 0.f);
#pragma unroll
    for (int ks = 0; ks < 8; ks++) {
        wmma::fragment<wmma::matrix_a, 16, 16, 16, __half, wmma::row_major> fah, fal;
        wmma::load_matrix_sync(fah, sAhi + mrow * 136 + ks * 16, 136);
        wmma::load_matrix_sync(fal, sAlo + mrow * 136 + ks * 16, 136);
#pragma unroll
        for (int ct = 0; ct < 2; ct++) {
            wmma::fragment<wmma::matrix_b, 16, 16, 16, __half, wmma::row_major> fb;
            wmma::load_matrix_sync(fb, sW + (ks * 16) * 72 + ncol + ct * 16, 72);
            wmma::mma_sync(fc[ct], fah, fb, fc[ct]);
            wmma::mma_sync(fc[ct], fal, fb, fc[ct]);
        }
    }
    __syncthreads();
    float* stage = (float*)sAhi;  // 64 x 72
#pragma unroll
    for (int ct = 0; ct < 2; ct++)
        wmma::store_matrix_sync(stage + mrow * 72 + ncol + ct * 16, fc[ct], 72,
                                wmma::mem_row_major);
    __syncthreads();
    if (tid < 128) {
        int row = tid >> 1, o = tid & 1;
        int gr = row0 + row;
        if (gr < NN) {
            float s = b2[o];
            for (int k = 0; k < 64; k++) {
                float hv = stage[row * 72 + k] + b1[k];
                hv = hv > 0.f ? hv : 0.f;
                s += hv * w2[k * 2 + o];
            }
            out[(size_t)gr * 2 + o] = s;
        }
    }
}

// ---------------- host orchestration -----------------------------------------
extern "C" void kernel_launch(void* const* d_in, const int* in_sizes, int n_in,
                              void* d_out, int out_size) {
    const int* x = (const int*)d_in[0];
    const int* src = (const int*)d_in[1];
    const int* dst = (const int*)d_in[2];
    const float* snorm_n = (const float*)d_in[3];
    const float* embed = (const float*)d_in[5];
    const float* W[3] = {(const float*)d_in[6], (const float*)d_in[11], (const float*)d_in[16]};
    const float* al[3] = {(const float*)d_in[7], (const float*)d_in[12], (const float*)d_in[17]};
    const float* ar[3] = {(const float*)d_in[8], (const float*)d_in[13], (const float*)d_in[18]};
    const float* gamma[3] = {(const float*)d_in[9], (const float*)d_in[14], (const float*)d_in[19]};
    const float* beta[3] = {(const float*)d_in[10], (const float*)d_in[15], (const float*)d_in[20]};
    const float* cls1_w = (const float*)d_in[21];
    const float* cls1_b = (const float*)d_in[22];
    const float* cls2_w = (const float*)d_in[23];
    const float* cls2_b = (const float*)d_in[24];
    float* out = (float*)d_out;

    float *h0, *h1, *el, *er, *bnstat;
    __half* feath;
    int *deg, *rowptr, *cursor, *csr, *partial, *poff;
    cudaGetSymbolAddress((void**)&h0, g_h0);
    cudaGetSymbolAddress((void**)&h1, g_h1);
    cudaGetSymbolAddress((void**)&feath, g_feath);
    cudaGetSymbolAddress((void**)&el, g_el);
    cudaGetSymbolAddress((void**)&er, g_er);
    cudaGetSymbolAddress((void**)&bnstat, g_bnstat);
    cudaGetSymbolAddress((void**)&deg, g_deg);
    cudaGetSymbolAddress((void**)&rowptr, g_rowptr);
    cudaGetSymbolAddress((void**)&cursor, g_cursor);
    cudaGetSymbolAddress((void**)&csr, g_csr);
    cudaGetSymbolAddress((void**)&partial, g_partial);
    cudaGetSymbolAddress((void**)&poff, g_poff);

    const int GEMM_SMEM = (128 * 136 + 2 * 64 * 136) * 2;  // 69632
    const int CLS_SMEM  = (128 * 72 + 2 * 64 * 136) * 2;   // 53248
    static bool attr_done = false;
    static cudaStream_t s2 = nullptr;
    static cudaEvent_t evFork = nullptr, evJoin = nullptr;
    if (!attr_done) {
        cudaFuncSetAttribute(k_gemm<true>, cudaFuncAttributeMaxDynamicSharedMemorySize, GEMM_SMEM);
        cudaFuncSetAttribute(k_gemm<false>, cudaFuncAttributeMaxDynamicSharedMemorySize, GEMM_SMEM);
        cudaFuncSetAttribute(k_cls, cudaFuncAttributeMaxDynamicSharedMemorySize, CLS_SMEM);
        cudaStreamCreateWithFlags(&s2, cudaStreamNonBlocking);
        cudaEventCreateWithFlags(&evFork, cudaEventDisableTiming);
        cudaEventCreateWithFlags(&evJoin, cudaEventDisableTiming);
        attr_done = true;
    }
    const int NSCAN = (NN + 255) / 256;  // 196

    // Fork: CSR build + bnstat clear on side stream, overlapped with gemm0.
    cudaEventRecord(evFork, 0);
    cudaStreamWaitEvent(s2, evFork, 0);
    cudaMemsetAsync(deg, 0, NN * sizeof(int), s2);
    cudaMemsetAsync(bnstat, 0, 3 * 256 * sizeof(float), s2);
    k_hist<<<(EE + 255) / 256, 256, 0, s2>>>(dst, deg);
    k_scan1<<<NSCAN, 256, 0, s2>>>(deg, partial);
    k_scan2<<<1, 256, 0, s2>>>(partial, poff, NSCAN);
    k_scan3<<<NSCAN, 256, 0, s2>>>(deg, poff, rowptr, cursor);
    k_fill<<<(EE + 255) / 256, 256, 0, s2>>>(src, dst, cursor, csr);
    cudaEventRecord(evJoin, s2);

    // Main stream: layer-0 GEMM (independent of CSR).
    k_gemm<true><<<PGRID, 256, GEMM_SMEM>>>(nullptr, x, embed, W[0],
                                            nullptr, nullptr, nullptr,
                                            al[0], ar[0], feath, el, er);
    cudaStreamWaitEvent(0, evJoin, 0);

    k_agg<false, false><<<NN / 8, 256>>>(feath, nullptr, (const float4*)el,
                                         (const float4*)er, snorm_n, rowptr, csr,
                                         h0, &bnstat[0], nullptr, nullptr, nullptr);
    // layer 1
    k_gemm<false><<<PGRID, 256, GEMM_SMEM>>>(h0, nullptr, nullptr, W[1],
                                             &bnstat[0], gamma[0], beta[0],
                                             al[1], ar[1], feath, el, er);
    k_agg<true, true><<<NN / 8, 256>>>(feath, h0, (const float4*)el,
                                       (const float4*)er, snorm_n, rowptr, csr,
                                       h1, &bnstat[256], &bnstat[0], gamma[0], beta[0]);
    // layer 2
    k_gemm<false><<<PGRID, 256, GEMM_SMEM>>>(h1, nullptr, nullptr, W[2],
                                             &bnstat[256], gamma[1], beta[1],
                                             al[2], ar[2], feath, el, er);
    k_agg<true, true><<<NN / 8, 256>>>(feath, h1, (const float4*)el,
                                       (const float4*)er, snorm_n, rowptr, csr,
                                       h0, &bnstat[512], &bnstat[256], gamma[1], beta[1]);
    // classifier
    k_cls<<<(NN + 63) / 64, 256, CLS_SMEM>>>(h0, cls1_w, cls1_b, cls2_w, cls2_b,
                                             &bnstat[512], gamma[2], beta[2], out);
}

// round 15
// speedup vs baseline: 1.1298x; 1.0180x over previous
#include <cuda_runtime.h>
#include <cuda_fp16.h>
#include <mma.h>
using namespace nvcuda;

#define NN 50000
#define EE 850000
#define NTILES 782   // ceil(NN/64)
#define PGRID 444

// ---------------- scratch (device globals) ----------------------------------
__device__ float  g_h0[NN * 128];
__device__ float  g_h1[NN * 128];
__device__ __half g_feath[NN * 128];
__device__ float  g_el[NN * 4];
__device__ float  g_er[NN * 4];
__device__ int    g_deg[NN];
__device__ int    g_rowptr[NN + 1];
__device__ int    g_cursor[NN];
__device__ int    g_csr[EE];
__device__ int    g_partial[256];
__device__ int    g_poff[256];
__device__ float  g_bnstat[3 * 256];

__device__ __forceinline__ float eluf(float x) { return x > 0.f ? x : (__expf(x) - 1.f); }
__device__ __forceinline__ float lrelu(float x) { return x > 0.f ? x : 0.2f * x; }

__device__ __forceinline__ void split2h(float v, __half& hi, __half& lo) {
    hi = __float2half_rn(v);
    lo = __float2half_rn(v - __half2float(hi));
}

// ---------------- CSR build --------------------------------------------------
__global__ void k_hist(const int* __restrict__ dst, int* deg) {
    int i = blockIdx.x * blockDim.x + threadIdx.x;
    if (i < EE) atomicAdd(&deg[dst[i]], 1);
}

__device__ __forceinline__ int block_scan_excl(int v, int t) {
    __shared__ int ws[8];
    int lane = t & 31, w = t >> 5;
    int incl = v;
#pragma unroll
    for (int o = 1; o < 32; o <<= 1) {
        int u = __shfl_up_sync(0xffffffffu, incl, o);
        if (lane >= o) incl += u;
    }
    if (lane == 31) ws[w] = incl;
    __syncthreads();
    if (t == 0) {
        int run = 0;
#pragma unroll
        for (int i = 0; i < 8; i++) { int x = ws[i]; ws[i] = run; run += x; }
    }
    __syncthreads();
    return incl - v + ws[w];
}

__global__ void k_scan1(const int* __restrict__ deg, int* __restrict__ partial) {
    __shared__ int ws[8];
    int t = threadIdx.x, idx = blockIdx.x * 256 + t;
    int v = (idx < NN) ? deg[idx] : 0;
#pragma unroll
    for (int o = 16; o > 0; o >>= 1) v += __shfl_xor_sync(0xffffffffu, v, o);
    if ((t & 31) == 0) ws[t >> 5] = v;
    __syncthreads();
    if (t == 0) {
        int s = 0;
#pragma unroll
        for (int i = 0; i < 8; i++) s += ws[i];
        partial[blockIdx.x] = s;
    }
}

__global__ void k_scan2(const int* __restrict__ partial, int* __restrict__ poff, int nblk) {
    int t = threadIdx.x;
    int v = (t < nblk) ? partial[t] : 0;
    int excl = block_scan_excl(v, t);
    if (t < nblk) poff[t] = excl;
}

__global__ void k_scan3(const int* __restrict__ deg, const int* __restrict__ poff,
                        int* __restrict__ rowptr, int* __restrict__ cursor) {
    int t = threadIdx.x, idx = blockIdx.x * 256 + t;
    int v = (idx < NN) ? deg[idx] : 0;
    int excl = block_scan_excl(v, t);
    int res = poff[blockIdx.x] + excl;
    if (idx <= NN) rowptr[idx] = res;
    if (idx < NN) cursor[idx] = res;
}

__global__ void k_fill(const int* __restrict__ src, const int* __restrict__ dst,
                       int* cursor, int* __restrict__ csr) {
    int i = blockIdx.x * blockDim.x + threadIdx.x;
    if (i < EE) {
        int d = dst[i];
        int pos = atomicAdd(&cursor[d], 1);
        csr[pos] = src[i];
    }
}

// ---------------- persistent HMMA GEMM (64-row tiles) + fused el/er ----------
template <bool L0>
__global__ void k_gemm(const float* __restrict__ A, const int* __restrict__ xidx,
                       const float* __restrict__ embed, const float* __restrict__ W,
                       const float* __restrict__ stat, const float* __restrict__ gamma,
                       const float* __restrict__ beta, const float* __restrict__ alv,
                       const float* __restrict__ arv, __half* __restrict__ feat,
                       float* __restrict__ el, float* __restrict__ er) {
    extern __shared__ __half smh[];
    __half* sW   = smh;                    // 128 x 136
    __half* sAhi = sW + 128 * 136;         // 64 x 136
    __half* sAlo = sAhi + 64 * 136;        // 64 x 136
    __shared__ float sc[128], shf[128];
    __shared__ float s_al[128], s_ar[128];
    int tid = threadIdx.x, warp = tid >> 5;

    if (!L0) {
        if (tid < 128) {
            float mu = stat[tid] * (1.f / NN);
            float var = stat[128 + tid] * (1.f / NN) - mu * mu;
            float r = rsqrtf(var + 1e-5f);
            sc[tid] = gamma[tid] * r;
            shf[tid] = beta[tid] - mu * gamma[tid] * r;
        }
    }
    if (tid < 128) { s_al[tid] = alv[tid]; s_ar[tid] = arv[tid]; }

    for (int p = tid; p < 4096; p += 256) {
        int r = p >> 5, c = (p & 31) * 4;
        float4 v = *(const float4*)&W[(size_t)r * 128 + c];
        sW[r * 136 + c]     = __float2half_rn(v.x);
        sW[r * 136 + c + 1] = __float2half_rn(v.y);
        sW[r * 136 + c + 2] = __float2half_rn(v.z);
        sW[r * 136 + c + 3] = __float2half_rn(v.w);
    }

    int mrow = (warp & 3) * 16;
    int ncol = (warp >> 2) * 64;

    for (int tile = blockIdx.x; tile < NTILES; tile += gridDim.x) {
        int row0 = tile * 64;
        __syncthreads();   // W ready / stage consumed
        for (int p = tid; p < 2048; p += 256) {
            int row = p >> 5, c = (p & 31) * 4;
            int gr = row0 + row;
            float4 v = make_float4(0.f, 0.f, 0.f, 0.f);
            if (gr < NN) {
                if (L0) v = *(const float4*)&embed[(size_t)xidx[gr] * 128 + c];
                else {
                    v = *(const float4*)&A[(size_t)gr * 128 + c];
                    v.x = eluf(v.x * sc[c] + shf[c]);
                    v.y = eluf(v.y * sc[c + 1] + shf[c + 1]);
                    v.z = eluf(v.z * sc[c + 2] + shf[c + 2]);
                    v.w = eluf(v.w * sc[c + 3] + shf[c + 3]);
                }
            }
            split2h(v.x, sAhi[row * 136 + c], sAlo[row * 136 + c]);
            split2h(v.y, sAhi[row * 136 + c + 1], sAlo[row * 136 + c + 1]);
            split2h(v.z, sAhi[row * 136 + c + 2], sAlo[row * 136 + c + 2]);
            split2h(v.w, sAhi[row * 136 + c + 3], sAlo[row * 136 + c + 3]);
        }
        __syncthreads();

        wmma::fragment<wmma::accumulator, 16, 16, 16, float> fc[4];
#pragma unroll
        for (int i = 0; i < 4; i++) wmma::fill_fragment(fc[i], 0.f);
#pragma unroll
        for (int ks = 0; ks < 8; ks++) {
            wmma::fragment<wmma::matrix_a, 16, 16, 16, __half, wmma::row_major> fah, fal;
            wmma::load_matrix_sync(fah, sAhi + mrow * 136 + ks * 16, 136);
            wmma::load_matrix_sync(fal, sAlo + mrow * 136 + ks * 16, 136);
#pragma unroll
            for (int ct = 0; ct < 4; ct++) {
                wmma::fragment<wmma::matrix_b, 16, 16, 16, __half, wmma::row_major> fb;
                wmma::load_matrix_sync(fb, sW + (ks * 16) * 136 + ncol + ct * 16, 136);
                wmma::mma_sync(fc[ct], fah, fb, fc[ct]);
                wmma::mma_sync(fc[ct], fal, fb, fc[ct]);
            }
        }
        __syncthreads();   // A reads done
        float* stage = (float*)sAhi;   // 64 x 136 floats
#pragma unroll
        for (int ct = 0; ct < 4; ct++)
            wmma::store_matrix_sync(stage + mrow * 136 + ncol + ct * 16, fc[ct], 136,
                                    wmma::mem_row_major);
        __syncthreads();

        // feat store + fused el/er
        for (int p = tid; p < 1024; p += 256) {
            int row = p >> 4, c8 = (p & 15) * 8;
            int gr = row0 + row;
            const float* s = stage + row * 136 + c8;
            float s0 = s[0], s1 = s[1], s2 = s[2], s3 = s[3];
            float s4 = s[4], s5 = s[5], s6 = s[6], s7 = s[7];
            if (gr < NN) {
                __half2 h0 = __floats2half2_rn(s0, s1);
                __half2 h1 = __floats2half2_rn(s2, s3);
                __half2 h2 = __floats2half2_rn(s4, s5);
                __half2 h3 = __floats2half2_rn(s6, s7);
                uint4 pack;
                pack.x = *(unsigned*)&h0; pack.y = *(unsigned*)&h1;
                pack.z = *(unsigned*)&h2; pack.w = *(unsigned*)&h3;
                *(uint4*)(feat + (size_t)gr * 128 + c8) = pack;
            }
            int h = c8 >> 5;
            const float* al8 = s_al + c8;
            const float* ar8 = s_ar + c8;
            float pl = s0 * al8[0] + s1 * al8[1] + s2 * al8[2] + s3 * al8[3]
                     + s4 * al8[4] + s5 * al8[5] + s6 * al8[6] + s7 * al8[7];
            float pr = s0 * ar8[0] + s1 * ar8[1] + s2 * ar8[2] + s3 * ar8[3]
                     + s4 * ar8[4] + s5 * ar8[5] + s6 * ar8[6] + s7 * ar8[7];
            pl += __shfl_xor_sync(0xffffffffu, pl, 1);
            pl += __shfl_xor_sync(0xffffffffu, pl, 2);
            pr += __shfl_xor_sync(0xffffffffu, pr, 1);
            pr += __shfl_xor_sync(0xffffffffu, pr, 2);
            if ((p & 3) == 0 && gr < NN) {
                el[gr * 4 + h] = pl;
                er[gr * 4 + h] = pr;
            }
        }
    }
}

// ---------------- fused softmax (max-free) + aggregation + BN stats ----------
template <bool RES, bool ACT>
__global__ void k_agg(const __half* __restrict__ feat, const float* __restrict__ hin,
                      const float4* __restrict__ el4, const float4* __restrict__ er4,
                      const float* __restrict__ snorm, const int* __restrict__ rowptr,
                      const int* __restrict__ csr, float* __restrict__ out,
                      float* __restrict__ bnstat, const float* __restrict__ pstat,
                      const float* __restrict__ pgamma, const float* __restrict__ pbeta) {
    __shared__ int   s_sj[8][32];
    __shared__ float s_a[8][32][4];
    __shared__ float bs[1024];
    __shared__ float bq[1024];
    __shared__ float psc[128], psh[128];
    int warp = threadIdx.x >> 5;
    int lane = threadIdx.x & 31;
    int node = blockIdx.x * 8 + warp;   // NN % 8 == 0
    if (RES) {
        int t = threadIdx.x;
        if (t < 128) {
            float mu = pstat[t] * (1.f / NN);
            float var = pstat[128 + t] * (1.f / NN) - mu * mu;
            float r = rsqrtf(var + 1e-5f);
            psc[t] = pgamma[t] * r;
            psh[t] = pbeta[t] - mu * pgamma[t] * r;
        }
        __syncthreads();
    }
    int start = rowptr[node], end = rowptr[node + 1];
    int deg = end - start;
    float4 er = er4[node];
    int hl = lane >> 3;
    int c0 = lane * 4;

    float4 acc = make_float4(0.f, 0.f, 0.f, 0.f);
    if (RES) {
        float4 h = *(const float4*)&hin[(size_t)node * 128 + c0];
        acc.x = eluf(h.x * psc[c0] + psh[c0]);
        acc.y = eluf(h.y * psc[c0 + 1] + psh[c0 + 1]);
        acc.z = eluf(h.z * psc[c0 + 2] + psh[c0 + 2]);
        acc.w = eluf(h.w * psc[c0 + 3] + psh[c0 + 3]);
    }

    if (deg <= 32) {
        bool on = lane < deg;
        int s = on ? csr[start + lane] : 0;
        float4 ex = make_float4(0.f, 0.f, 0.f, 0.f);
        if (on) {
            float4 e = el4[s];
            ex.x = __expf(lrelu(e.x + er.x));
            ex.y = __expf(lrelu(e.y + er.y));
            ex.z = __expf(lrelu(e.z + er.z));
            ex.w = __expf(lrelu(e.w + er.w));
        }
        float4 sm4 = ex;
#pragma unroll
        for (int o = 16; o > 0; o >>= 1) {
            sm4.x += __shfl_xor_sync(0xffffffffu, sm4.x, o);
            sm4.y += __shfl_xor_sync(0xffffffffu, sm4.y, o);
            sm4.z += __shfl_xor_sync(0xffffffffu, sm4.z, o);
            sm4.w += __shfl_xor_sync(0xffffffffu, sm4.w, o);
        }
        s_sj[warp][lane] = s;
        float4 aex = make_float4(ex.x / sm4.x, ex.y / sm4.y, ex.z / sm4.z, ex.w / sm4.w);
        *(float4*)&s_a[warp][lane][0] = aex;
        __syncwarp();
        int j = 0;
        for (; j + 4 <= deg; j += 4) {
            int sj0 = s_sj[warp][j],     sj1 = s_sj[warp][j + 1];
            int sj2 = s_sj[warp][j + 2], sj3 = s_sj[warp][j + 3];
            float a0 = s_a[warp][j][hl],     a1 = s_a[warp][j + 1][hl];
            float a2 = s_a[warp][j + 2][hl], a3 = s_a[warp][j + 3][hl];
            uint2 r0 = *(const uint2*)(feat + (size_t)sj0 * 128 + c0);
            uint2 r1 = *(const uint2*)(feat + (size_t)sj1 * 128 + c0);
            uint2 r2 = *(const uint2*)(feat + (size_t)sj2 * 128 + c0);
            uint2 r3 = *(const uint2*)(feat + (size_t)sj3 * 128 + c0);
            float2 p0 = __half22float2(*(__half2*)&r0.x), q0 = __half22float2(*(__half2*)&r0.y);
            float2 p1 = __half22float2(*(__half2*)&r1.x), q1 = __half22float2(*(__half2*)&r1.y);
            float2 p2 = __half22float2(*(__half2*)&r2.x), q2 = __half22float2(*(__half2*)&r2.y);
            float2 p3 = __half22float2(*(__half2*)&r3.x), q3 = __half22float2(*(__half2*)&r3.y);
            acc.x += p0.x * a0 + p1.x * a1 + p2.x * a2 + p3.x * a3;
            acc.y += p0.y * a0 + p1.y * a1 + p2.y * a2 + p3.y * a3;
            acc.z += q0.x * a0 + q1.x * a1 + q2.x * a2 + q3.x * a3;
            acc.w += q0.y * a0 + q1.y * a1 + q2.y * a2 + q3.y * a3;
        }
        for (; j < deg; j++) {
            int sj = s_sj[warp][j];
            float a = s_a[warp][j][hl];
            uint2 raw = *(const uint2*)(feat + (size_t)sj * 128 + c0);
            float2 f01 = __half22float2(*(__half2*)&raw.x);
            float2 f23 = __half22float2(*(__half2*)&raw.y);
            acc.x += f01.x * a; acc.y += f01.y * a;
            acc.z += f23.x * a; acc.w += f23.y * a;
        }
    } else {
        float s0 = 0.f, s1 = 0.f, s2 = 0.f, s3 = 0.f;
        for (int k = start + lane; k < end; k += 32) {
            int s = csr[k];
            float4 e = el4[s];
            s0 += __expf(lrelu(e.x + er.x));
            s1 += __expf(lrelu(e.y + er.y));
            s2 += __expf(lrelu(e.z + er.z));
            s3 += __expf(lrelu(e.w + er.w));
        }
#pragma unroll
        for (int o = 16; o > 0; o >>= 1) {
            s0 += __shfl_xor_sync(0xffffffffu, s0, o);
            s1 += __shfl_xor_sync(0xffffffffu, s1, o);
            s2 += __shfl_xor_sync(0xffffffffu, s2, o);
            s3 += __shfl_xor_sync(0xffffffffu, s3, o);
        }
        float invh = 1.f / (hl == 0 ? s0 : hl == 1 ? s1 : hl == 2 ? s2 : s3);
        float erh = hl == 0 ? er.x : hl == 1 ? er.y : hl == 2 ? er.z : er.w;
        int k = start;
        for (; k + 4 <= end; k += 4) {
            int sj0 = csr[k], sj1 = csr[k + 1], sj2 = csr[k + 2], sj3 = csr[k + 3];
            float4 e0 = el4[sj0], e1 = el4[sj1], e2 = el4[sj2], e3 = el4[sj3];
            float ev0 = hl == 0 ? e0.x : hl == 1 ? e0.y : hl == 2 ? e0.z : e0.w;
            float ev1 = hl == 0 ? e1.x : hl == 1 ? e1.y : hl == 2 ? e1.z : e1.w;
            float ev2 = hl == 0 ? e2.x : hl == 1 ? e2.y : hl == 2 ? e2.z : e2.w;
            float ev3 = hl == 0 ? e3.x : hl == 1 ? e3.y : hl == 2 ? e3.z : e3.w;
            float a0 = __expf(lrelu(ev0 + erh)) * invh;
            float a1 = __expf(lrelu(ev1 + erh)) * invh;
            float a2 = __expf(lrelu(ev2 + erh)) * invh;
            float a3 = __expf(lrelu(ev3 + erh)) * invh;
            uint2 r0 = *(const uint2*)(feat + (size_t)sj0 * 128 + c0);
            uint2 r1 = *(const uint2*)(feat + (size_t)sj1 * 128 + c0);
            uint2 r2 = *(const uint2*)(feat + (size_t)sj2 * 128 + c0);
            uint2 r3 = *(const uint2*)(feat + (size_t)sj3 * 128 + c0);
            float2 p0 = __half22float2(*(__half2*)&r0.x), q0 = __half22float2(*(__half2*)&r0.y);
            float2 p1 = __half22float2(*(__half2*)&r1.x), q1 = __half22float2(*(__half2*)&r1.y);
            float2 p2 = __half22float2(*(__half2*)&r2.x), q2 = __half22float2(*(__half2*)&r2.y);
            float2 p3 = __half22float2(*(__half2*)&r3.x), q3 = __half22float2(*(__half2*)&r3.y);
            acc.x += p0.x * a0 + p1.x * a1 + p2.x * a2 + p3.x * a3;
            acc.y += p0.y * a0 + p1.y * a1 + p2.y * a2 + p3.y * a3;
            acc.z += q0.x * a0 + q1.x * a1 + q2.x * a2 + q3.x * a3;
            acc.w += q0.y * a0 + q1.y * a1 + q2.y * a2 + q3.y * a3;
        }
        for (; k < end; k++) {
            int s = csr[k];
            float4 e = el4[s];
            float ev = hl == 0 ? e.x : hl == 1 ? e.y : hl == 2 ? e.z : e.w;
            float a = __expf(lrelu(ev + erh)) * invh;
            uint2 raw = *(const uint2*)(feat + (size_t)s * 128 + c0);
            float2 f01 = __half22float2(*(__half2*)&raw.x);
            float2 f23 = __half22float2(*(__half2*)&raw.y);
            acc.x += f01.x * a; acc.y += f01.y * a;
            acc.z += f23.x * a; acc.w += f23.y * a;
        }
    }
    if (ACT) {
        acc.x = eluf(acc.x); acc.y = eluf(acc.y);
        acc.z = eluf(acc.z); acc.w = eluf(acc.w);
    }
    float sn = snorm[node];
    acc.x *= sn; acc.y *= sn; acc.z *= sn; acc.w *= sn;
    *(float4*)&out[(size_t)node * 128 + c0] = acc;

    ((float4*)bs)[warp * 32 + lane] = acc;
    ((float4*)bq)[warp * 32 + lane] =
        make_float4(acc.x * acc.x, acc.y * acc.y, acc.z * acc.z, acc.w * acc.w);
    __syncthreads();
    int t = threadIdx.x;
    if (t < 128) {
        float s = 0.f, q = 0.f;
#pragma unroll
        for (int w = 0; w < 8; w++) { s += bs[w * 128 + t]; q += bq[w * 128 + t]; }
        atomicAdd(&bnstat[t], s);
        atomicAdd(&bnstat[128 + t], q);
    }
}

// ---------------- classifier: HMMA 128->64 (A split, W fp16), then 64->2 -----
__global__ void k_cls(const float* __restrict__ H, const float* __restrict__ w1,
                      const float* __restrict__ b1, const float* __restrict__ w2,
                      const float* __restrict__ b2, const float* __restrict__ stat,
                      const float* __restrict__ gamma, const float* __restrict__ beta,
                      float* __restrict__ out) {
    extern __shared__ __half smh[];
    __half* sW   = smh;                  // 128 x 72
    __half* sAhi = sW + 128 * 72;        // 64 x 136
    __half* sAlo = sAhi + 64 * 136;      // 64 x 136
    __shared__ float sc[128], shf[128];
    int tid = threadIdx.x, warp = tid >> 5;
    int row0 = blockIdx.x * 64;
    if (tid < 128) {
        float mu = stat[tid] * (1.f / NN);
        float var = stat[128 + tid] * (1.f / NN) - mu * mu;
        float r = rsqrtf(var + 1e-5f);
        sc[tid] = gamma[tid] * r;
        shf[tid] = beta[tid] - mu * gamma[tid] * r;
    }
    __syncthreads();

    for (int p = tid; p < 2048; p += 256) {
        int r = p >> 4, c = (p & 15) * 4;
        float4 v = *(const float4*)&w1[(size_t)r * 64 + c];
        sW[r * 72 + c]     = __float2half_rn(v.x);
        sW[r * 72 + c + 1] = __float2half_rn(v.y);
        sW[r * 72 + c + 2] = __float2half_rn(v.z);
        sW[r * 72 + c + 3] = __float2half_rn(v.w);
    }
    for (int p = tid; p < 2048; p += 256) {
        int row = p >> 5, c = (p & 31) * 4;
        int gr = row0 + row;
        float4 v = make_float4(0.f, 0.f, 0.f, 0.f);
        if (gr < NN) {
            v = *(const float4*)&H[(size_t)gr * 128 + c];
            v.x = eluf(v.x * sc[c] + shf[c]);
            v.y = eluf(v.y * sc[c + 1] + shf[c + 1]);
            v.z = eluf(v.z * sc[c + 2] + shf[c + 2]);
            v.w = eluf(v.w * sc[c + 3] + shf[c + 3]);
        }
        split2h(v.x, sAhi[row * 136 + c], sAlo[row * 136 + c]);
        split2h(v.y, sAhi[row * 136 + c + 1], sAlo[row * 136 + c + 1]);
        split2h(v.z, sAhi[row * 136 + c + 2], sAlo[row * 136 + c + 2]);
        split2h(v.w, sAhi[row * 136 + c + 3], sAlo[row * 136 + c + 3]);
    }
    __syncthreads();

    int mrow = (warp & 3) * 16;
    int ncol = (warp >> 2) * 32;
    wmma::fragment<wmma::accumulator, 16, 16, 16, float> fc[2];
#pragma unroll
    for (int i = 0; i < 2; i++) wmma::fill_fragment(fc[i], 0.f);
#pragma unroll
    for (int ks = 0; ks < 8; ks++) {
        wmma::fragment<wmma::matrix_a, 16, 16, 16, __half, wmma::row_major> fah, fal;
        wmma::load_matrix_sync(fah, sAhi + mrow * 136 + ks * 16, 136);
        wmma::load_matrix_sync(fal, sAlo + mrow * 136 + ks * 16, 136);
#pragma unroll
        for (int ct = 0; ct < 2; ct++) {
            wmma::fragment<wmma::matrix_b, 16, 16, 16, __half, wmma::row_major> fb;
            wmma::load_matrix_sync(fb, sW + (ks * 16) * 72 + ncol + ct * 16, 72);
            wmma::mma_sync(fc[ct], fah, fb, fc[ct]);
            wmma::mma_sync(fc[ct], fal, fb, fc[ct]);
        }
    }
    __syncthreads();
    float* stage = (float*)sAhi;  // 64 x 72
#pragma unroll
    for (int ct = 0; ct < 2; ct++)
        wmma::store_matrix_sync(stage + mrow * 72 + ncol + ct * 16, fc[ct], 72,
                                wmma::mem_row_major);
    __syncthreads();
    if (tid < 128) {
        int row = tid >> 1, o = tid & 1;
        int gr = row0 + row;
        if (gr < NN) {
            float s = b2[o];
            for (int k = 0; k < 64; k++) {
                float hv = stage[row * 72 + k] + b1[k];
                hv = hv > 0.f ? hv : 0.f;
                s += hv * w2[k * 2 + o];
            }
            out[(size_t)gr * 2 + o] = s;
        }
    }
}

// ---------------- host orchestration -----------------------------------------
extern "C" void kernel_launch(void* const* d_in, const int* in_sizes, int n_in,
                              void* d_out, int out_size) {
    const int* x = (const int*)d_in[0];
    const int* src = (const int*)d_in[1];
    const int* dst = (const int*)d_in[2];
    const float* snorm_n = (const float*)d_in[3];
    const float* embed = (const float*)d_in[5];
    const float* W[3] = {(const float*)d_in[6], (const float*)d_in[11], (const float*)d_in[16]};
    const float* al[3] = {(const float*)d_in[7], (const float*)d_in[12], (const float*)d_in[17]};
    const float* ar[3] = {(const float*)d_in[8], (const float*)d_in[13], (const float*)d_in[18]};
    const float* gamma[3] = {(const float*)d_in[9], (const float*)d_in[14], (const float*)d_in[19]};
    const float* beta[3] = {(const float*)d_in[10], (const float*)d_in[15], (const float*)d_in[20]};
    const float* cls1_w = (const float*)d_in[21];
    const float* cls1_b = (const float*)d_in[22];
    const float* cls2_w = (const float*)d_in[23];
    const float* cls2_b = (const float*)d_in[24];
    float* out = (float*)d_out;

    float *h0, *h1, *el, *er, *bnstat;
    __half* feath;
    int *deg, *rowptr, *cursor, *csr, *partial, *poff;
    cudaGetSymbolAddress((void**)&h0, g_h0);
    cudaGetSymbolAddress((void**)&h1, g_h1);
    cudaGetSymbolAddress((void**)&feath, g_feath);
    cudaGetSymbolAddress((void**)&el, g_el);
    cudaGetSymbolAddress((void**)&er, g_er);
    cudaGetSymbolAddress((void**)&bnstat, g_bnstat);
    cudaGetSymbolAddress((void**)&deg, g_deg);
    cudaGetSymbolAddress((void**)&rowptr, g_rowptr);
    cudaGetSymbolAddress((void**)&cursor, g_cursor);
    cudaGetSymbolAddress((void**)&csr, g_csr);
    cudaGetSymbolAddress((void**)&partial, g_partial);
    cudaGetSymbolAddress((void**)&poff, g_poff);

    const int GEMM_SMEM = (128 * 136 + 2 * 64 * 136) * 2;  // 69632
    const int CLS_SMEM  = (128 * 72 + 2 * 64 * 136) * 2;   // 53248
    static bool attr_done = false;
    static cudaStream_t s2 = nullptr;
    static cudaEvent_t evFork = nullptr, evJoin = nullptr;
    if (!attr_done) {
        cudaFuncSetAttribute(k_gemm<true>, cudaFuncAttributeMaxDynamicSharedMemorySize, GEMM_SMEM);
        cudaFuncSetAttribute(k_gemm<false>, cudaFuncAttributeMaxDynamicSharedMemorySize, GEMM_SMEM);
        cudaFuncSetAttribute(k_cls, cudaFuncAttributeMaxDynamicSharedMemorySize, CLS_SMEM);
        cudaStreamCreateWithFlags(&s2, cudaStreamNonBlocking);
        cudaEventCreateWithFlags(&evFork, cudaEventDisableTiming);
        cudaEventCreateWithFlags(&evJoin, cudaEventDisableTiming);
        attr_done = true;
    }
    const int NSCAN = (NN + 255) / 256;  // 196

    // Fork: CSR build on side stream, overlapped with layer-0 GEMM on main.
    cudaEventRecord(evFork, 0);
    cudaStreamWaitEvent(s2, evFork, 0);
    cudaMemsetAsync(deg, 0, NN * sizeof(int), s2);
    k_hist<<<(EE + 255) / 256, 256, 0, s2>>>(dst, deg);
    k_scan1<<<NSCAN, 256, 0, s2>>>(deg, partial);
    k_scan2<<<1, 256, 0, s2>>>(partial, poff, NSCAN);
    k_scan3<<<NSCAN, 256, 0, s2>>>(deg, poff, rowptr, cursor);
    k_fill<<<(EE + 255) / 256, 256, 0, s2>>>(src, dst, cursor, csr);
    cudaEventRecord(evJoin, s2);

    // Main stream: layer-0 GEMM (independent of CSR).
    cudaMemsetAsync(bnstat, 0, 3 * 256 * sizeof(float), 0);
    k_gemm<true><<<PGRID, 256, GEMM_SMEM>>>(nullptr, x, embed, W[0],
                                            nullptr, nullptr, nullptr,
                                            al[0], ar[0], feath, el, er);
    cudaStreamWaitEvent(0, evJoin, 0);

    k_agg<false, false><<<NN / 8, 256>>>(feath, nullptr, (const float4*)el,
                                         (const float4*)er, snorm_n, rowptr, csr,
                                         h0, &bnstat[0], nullptr, nullptr, nullptr);
    // layer 1
    k_gemm<false><<<PGRID, 256, GEMM_SMEM>>>(h0, nullptr, nullptr, W[1],
                                             &bnstat[0], gamma[0], beta[0],
                                             al[1], ar[1], feath, el, er);
    k_agg<true, true><<<NN / 8, 256>>>(feath, h0, (const float4*)el,
                                       (const float4*)er, snorm_n, rowptr, csr,
                                       h1, &bnstat[256], &bnstat[0], gamma[0], beta[0]);
    // layer 2
    k_gemm<false><<<PGRID, 256, GEMM_SMEM>>>(h1, nullptr, nullptr, W[2],
                                             &bnstat[256], gamma[1], beta[1],
                                             al[2], ar[2], feath, el, er);
    k_agg<true, true><<<NN / 8, 256>>>(feath, h1, (const float4*)el,
                                       (const float4*)er, snorm_n, rowptr, csr,
                                       h0, &bnstat[512], &bnstat[256], gamma[1], beta[1]);
    // classifier
    k_cls<<<(NN + 63) / 64, 256, CLS_SMEM>>>(h0, cls1_w, cls1_b, cls2_w, cls2_b,
                                             &bnstat[512], gamma[2], beta[2], out);
}

// round 16
// speedup vs baseline: 1.1363x; 1.0057x over previous
#include <cuda_runtime.h>
#include <cuda_fp16.h>
#include <mma.h>
using namespace nvcuda;

#define NN 50000
#define EE 850000
#define NTILES 782   // ceil(NN/64)
#define PGRID 456    // 152 SMs x 3 CTAs (GB300 has 152 SMs)

// ---------------- scratch (device globals) ----------------------------------
__device__ float  g_h0[NN * 128];
__device__ float  g_h1[NN * 128];
__device__ __half g_feath[NN * 128];
__device__ float  g_el[NN * 4];
__device__ float  g_er[NN * 4];
__device__ int    g_deg[NN];
__device__ int    g_rowptr[NN + 1];
__device__ int    g_cursor[NN];
__device__ int    g_csr[EE];
__device__ int    g_partial[256];
__device__ int    g_poff[256];
__device__ float  g_bnstat[3 * 256];

__device__ __forceinline__ float eluf(float x) { return x > 0.f ? x : (__expf(x) - 1.f); }
__device__ __forceinline__ float lrelu(float x) { return x > 0.f ? x : 0.2f * x; }

__device__ __forceinline__ void split2h(float v, __half& hi, __half& lo) {
    hi = __float2half_rn(v);
    lo = __float2half_rn(v - __half2float(hi));
}

// ---------------- CSR build --------------------------------------------------
__global__ void k_hist(const int* __restrict__ dst, int* deg) {
    int i = blockIdx.x * blockDim.x + threadIdx.x;
    if (i < EE) atomicAdd(&deg[dst[i]], 1);
}

__device__ __forceinline__ int block_scan_excl(int v, int t) {
    __shared__ int ws[8];
    int lane = t & 31, w = t >> 5;
    int incl = v;
#pragma unroll
    for (int o = 1; o < 32; o <<= 1) {
        int u = __shfl_up_sync(0xffffffffu, incl, o);
        if (lane >= o) incl += u;
    }
    if (lane == 31) ws[w] = incl;
    __syncthreads();
    if (t == 0) {
        int run = 0;
#pragma unroll
        for (int i = 0; i < 8; i++) { int x = ws[i]; ws[i] = run; run += x; }
    }
    __syncthreads();
    return incl - v + ws[w];
}

__global__ void k_scan1(const int* __restrict__ deg, int* __restrict__ partial) {
    __shared__ int ws[8];
    int t = threadIdx.x, idx = blockIdx.x * 256 + t;
    int v = (idx < NN) ? deg[idx] : 0;
#pragma unroll
    for (int o = 16; o > 0; o >>= 1) v += __shfl_xor_sync(0xffffffffu, v, o);
    if ((t & 31) == 0) ws[t >> 5] = v;
    __syncthreads();
    if (t == 0) {
        int s = 0;
#pragma unroll
        for (int i = 0; i < 8; i++) s += ws[i];
        partial[blockIdx.x] = s;
    }
}

__global__ void k_scan2(const int* __restrict__ partial, int* __restrict__ poff, int nblk) {
    int t = threadIdx.x;
    int v = (t < nblk) ? partial[t] : 0;
    int excl = block_scan_excl(v, t);
    if (t < nblk) poff[t] = excl;
}

__global__ void k_scan3(const int* __restrict__ deg, const int* __restrict__ poff,
                        int* __restrict__ rowptr, int* __restrict__ cursor) {
    int t = threadIdx.x, idx = blockIdx.x * 256 + t;
    int v = (idx < NN) ? deg[idx] : 0;
    int excl = block_scan_excl(v, t);
    int res = poff[blockIdx.x] + excl;
    if (idx <= NN) rowptr[idx] = res;
    if (idx < NN) cursor[idx] = res;
}

__global__ void k_fill(const int* __restrict__ src, const int* __restrict__ dst,
                       int* cursor, int* __restrict__ csr) {
    int i = blockIdx.x * blockDim.x + threadIdx.x;
    if (i < EE) {
        int d = dst[i];
        int pos = atomicAdd(&cursor[d], 1);
        csr[pos] = src[i];
    }
}

// ---------------- persistent HMMA GEMM (64-row tiles) + fused el/er ----------
template <bool L0>
__global__ void k_gemm(const float* __restrict__ A, const int* __restrict__ xidx,
                       const float* __restrict__ embed, const float* __restrict__ W,
                       const float* __restrict__ stat, const float* __restrict__ gamma,
                       const float* __restrict__ beta, const float* __restrict__ alv,
                       const float* __restrict__ arv, __half* __restrict__ feat,
                       float* __restrict__ el, float* __restrict__ er) {
    extern __shared__ __half smh[];
    __half* sW   = smh;                    // 128 x 136
    __half* sAhi = sW + 128 * 136;         // 64 x 136
    __half* sAlo = sAhi + 64 * 136;        // 64 x 136
    __shared__ float sc[128], shf[128];
    __shared__ float s_al[128], s_ar[128];
    int tid = threadIdx.x, warp = tid >> 5;

    if (!L0) {
        if (tid < 128) {
            float mu = stat[tid] * (1.f / NN);
            float var = stat[128 + tid] * (1.f / NN) - mu * mu;
            float r = rsqrtf(var + 1e-5f);
            sc[tid] = gamma[tid] * r;
            shf[tid] = beta[tid] - mu * gamma[tid] * r;
        }
    }
    if (tid < 128) { s_al[tid] = alv[tid]; s_ar[tid] = arv[tid]; }

    for (int p = tid; p < 4096; p += 256) {
        int r = p >> 5, c = (p & 31) * 4;
        float4 v = *(const float4*)&W[(size_t)r * 128 + c];
        sW[r * 136 + c]     = __float2half_rn(v.x);
        sW[r * 136 + c + 1] = __float2half_rn(v.y);
        sW[r * 136 + c + 2] = __float2half_rn(v.z);
        sW[r * 136 + c + 3] = __float2half_rn(v.w);
    }

    int mrow = (warp & 3) * 16;
    int ncol = (warp >> 2) * 64;

    for (int tile = blockIdx.x; tile < NTILES; tile += gridDim.x) {
        int row0 = tile * 64;
        __syncthreads();   // W ready / stage consumed
        for (int p = tid; p < 2048; p += 256) {
            int row = p >> 5, c = (p & 31) * 4;
            int gr = row0 + row;
            float4 v = make_float4(0.f, 0.f, 0.f, 0.f);
            if (gr < NN) {
                if (L0) v = *(const float4*)&embed[(size_t)xidx[gr] * 128 + c];
                else {
                    v = *(const float4*)&A[(size_t)gr * 128 + c];
                    v.x = eluf(v.x * sc[c] + shf[c]);
                    v.y = eluf(v.y * sc[c + 1] + shf[c + 1]);
                    v.z = eluf(v.z * sc[c + 2] + shf[c + 2]);
                    v.w = eluf(v.w * sc[c + 3] + shf[c + 3]);
                }
            }
            split2h(v.x, sAhi[row * 136 + c], sAlo[row * 136 + c]);
            split2h(v.y, sAhi[row * 136 + c + 1], sAlo[row * 136 + c + 1]);
            split2h(v.z, sAhi[row * 136 + c + 2], sAlo[row * 136 + c + 2]);
            split2h(v.w, sAhi[row * 136 + c + 3], sAlo[row * 136 + c + 3]);
        }
        __syncthreads();

        wmma::fragment<wmma::accumulator, 16, 16, 16, float> fc[4];
#pragma unroll
        for (int i = 0; i < 4; i++) wmma::fill_fragment(fc[i], 0.f);
#pragma unroll
        for (int ks = 0; ks < 8; ks++) {
            wmma::fragment<wmma::matrix_a, 16, 16, 16, __half, wmma::row_major> fah, fal;
            wmma::load_matrix_sync(fah, sAhi + mrow * 136 + ks * 16, 136);
            wmma::load_matrix_sync(fal, sAlo + mrow * 136 + ks * 16, 136);
#pragma unroll
            for (int ct = 0; ct < 4; ct++) {
                wmma::fragment<wmma::matrix_b, 16, 16, 16, __half, wmma::row_major> fb;
                wmma::load_matrix_sync(fb, sW + (ks * 16) * 136 + ncol + ct * 16, 136);
                wmma::mma_sync(fc[ct], fah, fb, fc[ct]);
                wmma::mma_sync(fc[ct], fal, fb, fc[ct]);
            }
        }
        __syncthreads();   // A reads done
        float* stage = (float*)sAhi;   // 64 x 136 floats
#pragma unroll
        for (int ct = 0; ct < 4; ct++)
            wmma::store_matrix_sync(stage + mrow * 136 + ncol + ct * 16, fc[ct], 136,
                                    wmma::mem_row_major);
        __syncthreads();

        // feat store + fused el/er
        for (int p = tid; p < 1024; p += 256) {
            int row = p >> 4, c8 = (p & 15) * 8;
            int gr = row0 + row;
            const float* s = stage + row * 136 + c8;
            float s0 = s[0], s1 = s[1], s2 = s[2], s3 = s[3];
            float s4 = s[4], s5 = s[5], s6 = s[6], s7 = s[7];
            if (gr < NN) {
                __half2 h0 = __floats2half2_rn(s0, s1);
                __half2 h1 = __floats2half2_rn(s2, s3);
                __half2 h2 = __floats2half2_rn(s4, s5);
                __half2 h3 = __floats2half2_rn(s6, s7);
                uint4 pack;
                pack.x = *(unsigned*)&h0; pack.y = *(unsigned*)&h1;
                pack.z = *(unsigned*)&h2; pack.w = *(unsigned*)&h3;
                *(uint4*)(feat + (size_t)gr * 128 + c8) = pack;
            }
            int h = c8 >> 5;
            const float* al8 = s_al + c8;
            const float* ar8 = s_ar + c8;
            float pl = s0 * al8[0] + s1 * al8[1] + s2 * al8[2] + s3 * al8[3]
                     + s4 * al8[4] + s5 * al8[5] + s6 * al8[6] + s7 * al8[7];
            float pr = s0 * ar8[0] + s1 * ar8[1] + s2 * ar8[2] + s3 * ar8[3]
                     + s4 * ar8[4] + s5 * ar8[5] + s6 * ar8[6] + s7 * ar8[7];
            pl += __shfl_xor_sync(0xffffffffu, pl, 1);
            pl += __shfl_xor_sync(0xffffffffu, pl, 2);
            pr += __shfl_xor_sync(0xffffffffu, pr, 1);
            pr += __shfl_xor_sync(0xffffffffu, pr, 2);
            if ((p & 3) == 0 && gr < NN) {
                el[gr * 4 + h] = pl;
                er[gr * 4 + h] = pr;
            }
        }
    }
}

// ---------------- fused softmax (max-free) + aggregation + BN stats ----------
template <bool RES, bool ACT>
__global__ void k_agg(const __half* __restrict__ feat, const float* __restrict__ hin,
                      const float4* __restrict__ el4, const float4* __restrict__ er4,
                      const float* __restrict__ snorm, const int* __restrict__ rowptr,
                      const int* __restrict__ csr, float* __restrict__ out,
                      float* __restrict__ bnstat, const float* __restrict__ pstat,
                      const float* __restrict__ pgamma, const float* __restrict__ pbeta) {
    __shared__ int   s_sj[8][32];
    __shared__ float s_a[8][32][4];
    __shared__ float bs[1024];
    __shared__ float bq[1024];
    __shared__ float psc[128], psh[128];
    int warp = threadIdx.x >> 5;
    int lane = threadIdx.x & 31;
    int node = blockIdx.x * 8 + warp;   // NN % 8 == 0
    if (RES) {
        int t = threadIdx.x;
        if (t < 128) {
            float mu = pstat[t] * (1.f / NN);
            float var = pstat[128 + t] * (1.f / NN) - mu * mu;
            float r = rsqrtf(var + 1e-5f);
            psc[t] = pgamma[t] * r;
            psh[t] = pbeta[t] - mu * pgamma[t] * r;
        }
        __syncthreads();
    }
    int start = rowptr[node], end = rowptr[node + 1];
    int deg = end - start;
    float4 er = er4[node];
    int hl = lane >> 3;
    int c0 = lane * 4;

    float4 acc = make_float4(0.f, 0.f, 0.f, 0.f);
    if (RES) {
        float4 h = *(const float4*)&hin[(size_t)node * 128 + c0];
        acc.x = eluf(h.x * psc[c0] + psh[c0]);
        acc.y = eluf(h.y * psc[c0 + 1] + psh[c0 + 1]);
        acc.z = eluf(h.z * psc[c0 + 2] + psh[c0 + 2]);
        acc.w = eluf(h.w * psc[c0 + 3] + psh[c0 + 3]);
    }

    if (deg <= 32) {
        bool on = lane < deg;
        int s = on ? csr[start + lane] : 0;
        float4 ex = make_float4(0.f, 0.f, 0.f, 0.f);
        if (on) {
            float4 e = el4[s];
            ex.x = __expf(lrelu(e.x + er.x));
            ex.y = __expf(lrelu(e.y + er.y));
            ex.z = __expf(lrelu(e.z + er.z));
            ex.w = __expf(lrelu(e.w + er.w));
        }
        float4 sm4 = ex;
#pragma unroll
        for (int o = 16; o > 0; o >>= 1) {
            sm4.x += __shfl_xor_sync(0xffffffffu, sm4.x, o);
            sm4.y += __shfl_xor_sync(0xffffffffu, sm4.y, o);
            sm4.z += __shfl_xor_sync(0xffffffffu, sm4.z, o);
            sm4.w += __shfl_xor_sync(0xffffffffu, sm4.w, o);
        }
        s_sj[warp][lane] = s;
        float4 aex = make_float4(ex.x / sm4.x, ex.y / sm4.y, ex.z / sm4.z, ex.w / sm4.w);
        *(float4*)&s_a[warp][lane][0] = aex;
        __syncwarp();
        int j = 0;
        for (; j + 4 <= deg; j += 4) {
            int sj0 = s_sj[warp][j],     sj1 = s_sj[warp][j + 1];
            int sj2 = s_sj[warp][j + 2], sj3 = s_sj[warp][j + 3];
            float a0 = s_a[warp][j][hl],     a1 = s_a[warp][j + 1][hl];
            float a2 = s_a[warp][j + 2][hl], a3 = s_a[warp][j + 3][hl];
            uint2 r0 = *(const uint2*)(feat + (size_t)sj0 * 128 + c0);
            uint2 r1 = *(const uint2*)(feat + (size_t)sj1 * 128 + c0);
            uint2 r2 = *(const uint2*)(feat + (size_t)sj2 * 128 + c0);
            uint2 r3 = *(const uint2*)(feat + (size_t)sj3 * 128 + c0);
            float2 p0 = __half22float2(*(__half2*)&r0.x), q0 = __half22float2(*(__half2*)&r0.y);
            float2 p1 = __half22float2(*(__half2*)&r1.x), q1 = __half22float2(*(__half2*)&r1.y);
            float2 p2 = __half22float2(*(__half2*)&r2.x), q2 = __half22float2(*(__half2*)&r2.y);
            float2 p3 = __half22float2(*(__half2*)&r3.x), q3 = __half22float2(*(__half2*)&r3.y);
            acc.x += p0.x * a0 + p1.x * a1 + p2.x * a2 + p3.x * a3;
            acc.y += p0.y * a0 + p1.y * a1 + p2.y * a2 + p3.y * a3;
            acc.z += q0.x * a0 + q1.x * a1 + q2.x * a2 + q3.x * a3;
            acc.w += q0.y * a0 + q1.y * a1 + q2.y * a2 + q3.y * a3;
        }
        for (; j < deg; j++) {
            int sj = s_sj[warp][j];
            float a = s_a[warp][j][hl];
            uint2 raw = *(const uint2*)(feat + (size_t)sj * 128 + c0);
            float2 f01 = __half22float2(*(__half2*)&raw.x);
            float2 f23 = __half22float2(*(__half2*)&raw.y);
            acc.x += f01.x * a; acc.y += f01.y * a;
            acc.z += f23.x * a; acc.w += f23.y * a;
        }
    } else {
        float s0 = 0.f, s1 = 0.f, s2 = 0.f, s3 = 0.f;
        for (int k = start + lane; k < end; k += 32) {
            int s = csr[k];
            float4 e = el4[s];
            s0 += __expf(lrelu(e.x + er.x));
            s1 += __expf(lrelu(e.y + er.y));
            s2 += __expf(lrelu(e.z + er.z));
            s3 += __expf(lrelu(e.w + er.w));
        }
#pragma unroll
        for (int o = 16; o > 0; o >>= 1) {
            s0 += __shfl_xor_sync(0xffffffffu, s0, o);
            s1 += __shfl_xor_sync(0xffffffffu, s1, o);
            s2 += __shfl_xor_sync(0xffffffffu, s2, o);
            s3 += __shfl_xor_sync(0xffffffffu, s3, o);
        }
        float invh = 1.f / (hl == 0 ? s0 : hl == 1 ? s1 : hl == 2 ? s2 : s3);
        float erh = hl == 0 ? er.x : hl == 1 ? er.y : hl == 2 ? er.z : er.w;
        int k = start;
        for (; k + 4 <= end; k += 4) {
            int sj0 = csr[k], sj1 = csr[k + 1], sj2 = csr[k + 2], sj3 = csr[k + 3];
            float4 e0 = el4[sj0], e1 = el4[sj1], e2 = el4[sj2], e3 = el4[sj3];
            float ev0 = hl == 0 ? e0.x : hl == 1 ? e0.y : hl == 2 ? e0.z : e0.w;
            float ev1 = hl == 0 ? e1.x : hl == 1 ? e1.y : hl == 2 ? e1.z : e1.w;
            float ev2 = hl == 0 ? e2.x : hl == 1 ? e2.y : hl == 2 ? e2.z : e2.w;
            float ev3 = hl == 0 ? e3.x : hl == 1 ? e3.y : hl == 2 ? e3.z : e3.w;
            float a0 = __expf(lrelu(ev0 + erh)) * invh;
            float a1 = __expf(lrelu(ev1 + erh)) * invh;
            float a2 = __expf(lrelu(ev2 + erh)) * invh;
            float a3 = __expf(lrelu(ev3 + erh)) * invh;
            uint2 r0 = *(const uint2*)(feat + (size_t)sj0 * 128 + c0);
            uint2 r1 = *(const uint2*)(feat + (size_t)sj1 * 128 + c0);
            uint2 r2 = *(const uint2*)(feat + (size_t)sj2 * 128 + c0);
            uint2 r3 = *(const uint2*)(feat + (size_t)sj3 * 128 + c0);
            float2 p0 = __half22float2(*(__half2*)&r0.x), q0 = __half22float2(*(__half2*)&r0.y);
            float2 p1 = __half22float2(*(__half2*)&r1.x), q1 = __half22float2(*(__half2*)&r1.y);
            float2 p2 = __half22float2(*(__half2*)&r2.x), q2 = __half22float2(*(__half2*)&r2.y);
            float2 p3 = __half22float2(*(__half2*)&r3.x), q3 = __half22float2(*(__half2*)&r3.y);
            acc.x += p0.x * a0 + p1.x * a1 + p2.x * a2 + p3.x * a3;
            acc.y += p0.y * a0 + p1.y * a1 + p2.y * a2 + p3.y * a3;
            acc.z += q0.x * a0 + q1.x * a1 + q2.x * a2 + q3.x * a3;
            acc.w += q0.y * a0 + q1.y * a1 + q2.y * a2 + q3.y * a3;
        }
        for (; k < end; k++) {
            int s = csr[k];
            float4 e = el4[s];
            float ev = hl == 0 ? e.x : hl == 1 ? e.y : hl == 2 ? e.z : e.w;
            float a = __expf(lrelu(ev + erh)) * invh;
            uint2 raw = *(const uint2*)(feat + (size_t)s * 128 + c0);
            float2 f01 = __half22float2(*(__half2*)&raw.x);
            float2 f23 = __half22float2(*(__half2*)&raw.y);
            acc.x += f01.x * a; acc.y += f01.y * a;
            acc.z += f23.x * a; acc.w += f23.y * a;
        }
    }
    if (ACT) {
        acc.x = eluf(acc.x); acc.y = eluf(acc.y);
        acc.z = eluf(acc.z); acc.w = eluf(acc.w);
    }
    float sn = snorm[node];
    acc.x *= sn; acc.y *= sn; acc.z *= sn; acc.w *= sn;
    *(float4*)&out[(size_t)node * 128 + c0] = acc;

    ((float4*)bs)[warp * 32 + lane] = acc;
    ((float4*)bq)[warp * 32 + lane] =
        make_float4(acc.x * acc.x, acc.y * acc.y, acc.z * acc.z, acc.w * acc.w);
    __syncthreads();
    int t = threadIdx.x;
    if (t < 128) {
        float s = 0.f, q = 0.f;
#pragma unroll
        for (int w = 0; w < 8; w++) { s += bs[w * 128 + t]; q += bq[w * 128 + t]; }
        atomicAdd(&bnstat[t], s);
        atomicAdd(&bnstat[128 + t], q);
    }
}

// ---------------- classifier: HMMA 128->64 (A split, W fp16), then 64->2 -----
__global__ void k_cls(const float* __restrict__ H, const float* __restrict__ w1,
                      const float* __restrict__ b1, const float* __restrict__ w2,
                      const float* __restrict__ b2, const float* __restrict__ stat,
                      const float* __restrict__ gamma, const float* __restrict__ beta,
                      float* __restrict__ out) {
    extern __shared__ __half smh[];
    __half* sW   = smh;                  // 128 x 72
    __half* sAhi = sW + 128 * 72;        // 64 x 136
    __half* sAlo = sAhi + 64 * 136;      // 64 x 136
    __shared__ float sc[128], shf[128];
    int tid = threadIdx.x, warp = tid >> 5;
    int row0 = blockIdx.x * 64;
    if (tid < 128) {
        float mu = stat[tid] * (1.f / NN);
        float var = stat[128 + tid] * (1.f / NN) - mu * mu;
        float r = rsqrtf(var + 1e-5f);
        sc[tid] = gamma[tid] * r;
        shf[tid] = beta[tid] - mu * gamma[tid] * r;
    }
    __syncthreads();

    for (int p = tid; p < 2048; p += 256) {
        int r = p >> 4, c = (p & 15) * 4;
        float4 v = *(const float4*)&w1[(size_t)r * 64 + c];
        sW[r * 72 + c]     = __float2half_rn(v.x);
        sW[r * 72 + c + 1] = __float2half_rn(v.y);
        sW[r * 72 + c + 2] = __float2half_rn(v.z);
        sW[r * 72 + c + 3] = __float2half_rn(v.w);
    }
    for (int p = tid; p < 2048; p += 256) {
        int row = p >> 5, c = (p & 31) * 4;
        int gr = row0 + row;
        float4 v = make_float4(0.f, 0.f, 0.f, 0.f);
        if (gr < NN) {
            v = *(const float4*)&H[(size_t)gr * 128 + c];
            v.x = eluf(v.x * sc[c] + shf[c]);
            v.y = eluf(v.y * sc[c + 1] + shf[c + 1]);
            v.z = eluf(v.z * sc[c + 2] + shf[c + 2]);
            v.w = eluf(v.w * sc[c + 3] + shf[c + 3]);
        }
        split2h(v.x, sAhi[row * 136 + c], sAlo[row * 136 + c]);
        split2h(v.y, sAhi[row * 136 + c + 1], sAlo[row * 136 + c + 1]);
        split2h(v.z, sAhi[row * 136 + c + 2], sAlo[row * 136 + c + 2]);
        split2h(v.w, sAhi[row * 136 + c + 3], sAlo[row * 136 + c + 3]);
    }
    __syncthreads();

    int mrow = (warp & 3) * 16;
    int ncol = (warp >> 2) * 32;
    wmma::fragment<wmma::accumulator, 16, 16, 16, float> fc[2];
#pragma unroll
    for (int i = 0; i < 2; i++) wmma::fill_fragment(fc[i], 0.f);
#pragma unroll
    for (int ks = 0; ks < 8; ks++) {
        wmma::fragment<wmma::matrix_a, 16, 16, 16, __half, wmma::row_major> fah, fal;
        wmma::load_matrix_sync(fah, sAhi + mrow * 136 + ks * 16, 136);
        wmma::load_matrix_sync(fal, sAlo + mrow * 136 + ks * 16, 136);
#pragma unroll
        for (int ct = 0; ct < 2; ct++) {
            wmma::fragment<wmma::matrix_b, 16, 16, 16, __half, wmma::row_major> fb;
            wmma::load_matrix_sync(fb, sW + (ks * 16) * 72 + ncol + ct * 16, 72);
            wmma::mma_sync(fc[ct], fah, fb, fc[ct]);
            wmma::mma_sync(fc[ct], fal, fb, fc[ct]);
        }
    }
    __syncthreads();
    float* stage = (float*)sAhi;  // 64 x 72
#pragma unroll
    for (int ct = 0; ct < 2; ct++)
        wmma::store_matrix_sync(stage + mrow * 72 + ncol + ct * 16, fc[ct], 72,
                                wmma::mem_row_major);
    __syncthreads();
    if (tid < 128) {
        int row = tid >> 1, o = tid & 1;
        int gr = row0 + row;
        if (gr < NN) {
            float s = b2[o];
            for (int k = 0; k < 64; k++) {
                float hv = stage[row * 72 + k] + b1[k];
                hv = hv > 0.f ? hv : 0.f;
                s += hv * w2[k * 2 + o];
            }
            out[(size_t)gr * 2 + o] = s;
        }
    }
}

// ---------------- host orchestration -----------------------------------------
extern "C" void kernel_launch(void* const* d_in, const int* in_sizes, int n_in,
                              void* d_out, int out_size) {
    const int* x = (const int*)d_in[0];
    const int* src = (const int*)d_in[1];
    const int* dst = (const int*)d_in[2];
    const float* snorm_n = (const float*)d_in[3];
    const float* embed = (const float*)d_in[5];
    const float* W[3] = {(const float*)d_in[6], (const float*)d_in[11], (const float*)d_in[16]};
    const float* al[3] = {(const float*)d_in[7], (const float*)d_in[12], (const float*)d_in[17]};
    const float* ar[3] = {(const float*)d_in[8], (const float*)d_in[13], (const float*)d_in[18]};
    const float* gamma[3] = {(const float*)d_in[9], (const float*)d_in[14], (const float*)d_in[19]};
    const float* beta[3] = {(const float*)d_in[10], (const float*)d_in[15], (const float*)d_in[20]};
    const float* cls1_w = (const float*)d_in[21];
    const float* cls1_b = (const float*)d_in[22];
    const float* cls2_w = (const float*)d_in[23];
    const float* cls2_b = (const float*)d_in[24];
    float* out = (float*)d_out;

    float *h0, *h1, *el, *er, *bnstat;
    __half* feath;
    int *deg, *rowptr, *cursor, *csr, *partial, *poff;
    cudaGetSymbolAddress((void**)&h0, g_h0);
    cudaGetSymbolAddress((void**)&h1, g_h1);
    cudaGetSymbolAddress((void**)&feath, g_feath);
    cudaGetSymbolAddress((void**)&el, g_el);
    cudaGetSymbolAddress((void**)&er, g_er);
    cudaGetSymbolAddress((void**)&bnstat, g_bnstat);
    cudaGetSymbolAddress((void**)&deg, g_deg);
    cudaGetSymbolAddress((void**)&rowptr, g_rowptr);
    cudaGetSymbolAddress((void**)&cursor, g_cursor);
    cudaGetSymbolAddress((void**)&csr, g_csr);
    cudaGetSymbolAddress((void**)&partial, g_partial);
    cudaGetSymbolAddress((void**)&poff, g_poff);

    const int GEMM_SMEM = (128 * 136 + 2 * 64 * 136) * 2;  // 69632
    const int CLS_SMEM  = (128 * 72 + 2 * 64 * 136) * 2;   // 53248
    static bool attr_done = false;
    static cudaStream_t s2 = nullptr;
    static cudaEvent_t evFork = nullptr, evJoin = nullptr;
    if (!attr_done) {
        cudaFuncSetAttribute(k_gemm<true>, cudaFuncAttributeMaxDynamicSharedMemorySize, GEMM_SMEM);
        cudaFuncSetAttribute(k_gemm<false>, cudaFuncAttributeMaxDynamicSharedMemorySize, GEMM_SMEM);
        cudaFuncSetAttribute(k_cls, cudaFuncAttributeMaxDynamicSharedMemorySize, CLS_SMEM);
        cudaStreamCreateWithFlags(&s2, cudaStreamNonBlocking);
        cudaEventCreateWithFlags(&evFork, cudaEventDisableTiming);
        cudaEventCreateWithFlags(&evJoin, cudaEventDisableTiming);
        attr_done = true;
    }
    const int NSCAN = (NN + 255) / 256;  // 196

    // Fork: CSR build on side stream, overlapped with layer-0 GEMM on main.
    cudaEventRecord(evFork, 0);
    cudaStreamWaitEvent(s2, evFork, 0);
    cudaMemsetAsync(deg, 0, NN * sizeof(int), s2);
    k_hist<<<(EE + 255) / 256, 256, 0, s2>>>(dst, deg);
    k_scan1<<<NSCAN, 256, 0, s2>>>(deg, partial);
    k_scan2<<<1, 256, 0, s2>>>(partial, poff, NSCAN);
    k_scan3<<<NSCAN, 256, 0, s2>>>(deg, poff, rowptr, cursor);
    k_fill<<<(EE + 255) / 256, 256, 0, s2>>>(src, dst, cursor, csr);
    cudaEventRecord(evJoin, s2);

    // Main stream: layer-0 GEMM (independent of CSR).
    cudaMemsetAsync(bnstat, 0, 3 * 256 * sizeof(float), 0);
    k_gemm<true><<<PGRID, 256, GEMM_SMEM>>>(nullptr, x, embed, W[0],
                                            nullptr, nullptr, nullptr,
                                            al[0], ar[0], feath, el, er);
    cudaStreamWaitEvent(0, evJoin, 0);

    k_agg<false, false><<<NN / 8, 256>>>(feath, nullptr, (const float4*)el,
                                         (const float4*)er, snorm_n, rowptr, csr,
                                         h0, &bnstat[0], nullptr, nullptr, nullptr);
    // layer 1
    k_gemm<false><<<PGRID, 256, GEMM_SMEM>>>(h0, nullptr, nullptr, W[1],
                                             &bnstat[0], gamma[0], beta[0],
                                             al[1], ar[1], feath, el, er);
    k_agg<true, true><<<NN / 8, 256>>>(feath, h0, (const float4*)el,
                                       (const float4*)er, snorm_n, rowptr, csr,
                                       h1, &bnstat[256], &bnstat[0], gamma[0], beta[0]);
    // layer 2
    k_gemm<false><<<PGRID, 256, GEMM_SMEM>>>(h1, nullptr, nullptr, W[2],
                                             &bnstat[256], gamma[1], beta[1],
                                             al[2], ar[2], feath, el, er);
    k_agg<true, true><<<NN / 8, 256>>>(feath, h1, (const float4*)el,
                                       (const float4*)er, snorm_n, rowptr, csr,
                                       h0, &bnstat[512], &bnstat[256], gamma[1], beta[1]);
    // classifier
    k_cls<<<(NN + 63) / 64, 256, CLS_SMEM>>>(h0, cls1_w, cls1_b, cls2_w, cls2_b,
                                             &bnstat[512], gamma[2], beta[2], out);
}

// round 17
// speedup vs baseline: 1.1529x; 1.0146x over previous
#include <cuda_runtime.h>
#include <cuda_fp16.h>
#include <mma.h>
using namespace nvcuda;

#define NN 50000
#define EE 850000
#define NTILES 782   // ceil(NN/64)
#define PGRID 444

// ---------------- scratch (device globals) ----------------------------------
__device__ float  g_h0[NN * 128];
__device__ float  g_h1[NN * 128];
__device__ __half g_feath[NN * 128];
__device__ float  g_el[NN * 4];
__device__ float  g_er[NN * 4];
__device__ int    g_deg[NN];
__device__ int    g_rowptr[NN + 1];
__device__ int    g_cursor[NN];
__device__ int    g_csr[EE];
__device__ int    g_partial[256];
__device__ int    g_poff[256];
__device__ float  g_bnstat[3 * 256];

__device__ __forceinline__ float eluf(float x) { return x > 0.f ? x : (__expf(x) - 1.f); }
__device__ __forceinline__ float lrelu(float x) { return x > 0.f ? x : 0.2f * x; }

__device__ __forceinline__ void split2h(float v, __half& hi, __half& lo) {
    hi = __float2half_rn(v);
    lo = __float2half_rn(v - __half2float(hi));
}

// ---------------- CSR build --------------------------------------------------
__global__ void k_hist(const int* __restrict__ dst, int* deg) {
    int i = blockIdx.x * blockDim.x + threadIdx.x;
    if (i < EE) atomicAdd(&deg[dst[i]], 1);
}

__device__ __forceinline__ int block_scan_excl(int v, int t) {
    __shared__ int ws[8];
    int lane = t & 31, w = t >> 5;
    int incl = v;
#pragma unroll
    for (int o = 1; o < 32; o <<= 1) {
        int u = __shfl_up_sync(0xffffffffu, incl, o);
        if (lane >= o) incl += u;
    }
    if (lane == 31) ws[w] = incl;
    __syncthreads();
    if (t == 0) {
        int run = 0;
#pragma unroll
        for (int i = 0; i < 8; i++) { int x = ws[i]; ws[i] = run; run += x; }
    }
    __syncthreads();
    return incl - v + ws[w];
}

__global__ void k_scan1(const int* __restrict__ deg, int* __restrict__ partial) {
    __shared__ int ws[8];
    int t = threadIdx.x, idx = blockIdx.x * 256 + t;
    int v = (idx < NN) ? deg[idx] : 0;
#pragma unroll
    for (int o = 16; o > 0; o >>= 1) v += __shfl_xor_sync(0xffffffffu, v, o);
    if ((t & 31) == 0) ws[t >> 5] = v;
    __syncthreads();
    if (t == 0) {
        int s = 0;
#pragma unroll
        for (int i = 0; i < 8; i++) s += ws[i];
        partial[blockIdx.x] = s;
    }
}

__global__ void k_scan2(const int* __restrict__ partial, int* __restrict__ poff, int nblk) {
    int t = threadIdx.x;
    int v = (t < nblk) ? partial[t] : 0;
    int excl = block_scan_excl(v, t);
    if (t < nblk) poff[t] = excl;
}

__global__ void k_scan3(const int* __restrict__ deg, const int* __restrict__ poff,
                        int* __restrict__ rowptr, int* __restrict__ cursor) {
    int t = threadIdx.x, idx = blockIdx.x * 256 + t;
    int v = (idx < NN) ? deg[idx] : 0;
    int excl = block_scan_excl(v, t);
    int res = poff[blockIdx.x] + excl;
    if (idx <= NN) rowptr[idx] = res;
    if (idx < NN) cursor[idx] = res;
}

__global__ void k_fill(const int* __restrict__ src, const int* __restrict__ dst,
                       int* cursor, int* __restrict__ csr) {
    int i = blockIdx.x * blockDim.x + threadIdx.x;
    if (i < EE) {
        int d = dst[i];
        int pos = atomicAdd(&cursor[d], 1);
        csr[pos] = src[i];
    }
}

// ---------------- persistent HMMA GEMM (64-row tiles) + fused el/er ----------
template <bool L0>
__global__ void k_gemm(const float* __restrict__ A, const int* __restrict__ xidx,
                       const float* __restrict__ embed, const float* __restrict__ W,
                       const float* __restrict__ stat, const float* __restrict__ gamma,
                       const float* __restrict__ beta, const float* __restrict__ alv,
                       const float* __restrict__ arv, __half* __restrict__ feat,
                       float* __restrict__ el, float* __restrict__ er) {
    extern __shared__ __half smh[];
    __half* sW   = smh;                    // 128 x 136
    __half* sAhi = sW + 128 * 136;         // 64 x 136
    __half* sAlo = sAhi + 64 * 136;        // 64 x 136
    __shared__ float sc[128], shf[128];
    __shared__ float s_al[128], s_ar[128];
    int tid = threadIdx.x, warp = tid >> 5;

    if (!L0) {
        if (tid < 128) {
            float mu = stat[tid] * (1.f / NN);
            float var = stat[128 + tid] * (1.f / NN) - mu * mu;
            float r = rsqrtf(var + 1e-5f);
            sc[tid] = gamma[tid] * r;
            shf[tid] = beta[tid] - mu * gamma[tid] * r;
        }
    }
    if (tid < 128) { s_al[tid] = alv[tid]; s_ar[tid] = arv[tid]; }

    for (int p = tid; p < 4096; p += 256) {
        int r = p >> 5, c = (p & 31) * 4;
        float4 v = *(const float4*)&W[(size_t)r * 128 + c];
        sW[r * 136 + c]     = __float2half_rn(v.x);
        sW[r * 136 + c + 1] = __float2half_rn(v.y);
        sW[r * 136 + c + 2] = __float2half_rn(v.z);
        sW[r * 136 + c + 3] = __float2half_rn(v.w);
    }

    int mrow = (warp & 3) * 16;
    int ncol = (warp >> 2) * 64;

    for (int tile = blockIdx.x; tile < NTILES; tile += gridDim.x) {
        int row0 = tile * 64;
        __syncthreads();   // W ready / stage consumed
        for (int p = tid; p < 2048; p += 256) {
            int row = p >> 5, c = (p & 31) * 4;
            int gr = row0 + row;
            float4 v = make_float4(0.f, 0.f, 0.f, 0.f);
            if (gr < NN) {
                if (L0) v = *(const float4*)&embed[(size_t)xidx[gr] * 128 + c];
                else {
                    v = *(const float4*)&A[(size_t)gr * 128 + c];
                    v.x = eluf(v.x * sc[c] + shf[c]);
                    v.y = eluf(v.y * sc[c + 1] + shf[c + 1]);
                    v.z = eluf(v.z * sc[c + 2] + shf[c + 2]);
                    v.w = eluf(v.w * sc[c + 3] + shf[c + 3]);
                }
            }
            split2h(v.x, sAhi[row * 136 + c], sAlo[row * 136 + c]);
            split2h(v.y, sAhi[row * 136 + c + 1], sAlo[row * 136 + c + 1]);
            split2h(v.z, sAhi[row * 136 + c + 2], sAlo[row * 136 + c + 2]);
            split2h(v.w, sAhi[row * 136 + c + 3], sAlo[row * 136 + c + 3]);
        }
        __syncthreads();

        wmma::fragment<wmma::accumulator, 16, 16, 16, float> fc[4];
#pragma unroll
        for (int i = 0; i < 4; i++) wmma::fill_fragment(fc[i], 0.f);
#pragma unroll
        for (int ks = 0; ks < 8; ks++) {
            wmma::fragment<wmma::matrix_a, 16, 16, 16, __half, wmma::row_major> fah, fal;
            wmma::load_matrix_sync(fah, sAhi + mrow * 136 + ks * 16, 136);
            wmma::load_matrix_sync(fal, sAlo + mrow * 136 + ks * 16, 136);
#pragma unroll
            for (int ct = 0; ct < 4; ct++) {
                wmma::fragment<wmma::matrix_b, 16, 16, 16, __half, wmma::row_major> fb;
                wmma::load_matrix_sync(fb, sW + (ks * 16) * 136 + ncol + ct * 16, 136);
                wmma::mma_sync(fc[ct], fah, fb, fc[ct]);
                wmma::mma_sync(fc[ct], fal, fb, fc[ct]);
            }
        }
        __syncthreads();   // A reads done
        float* stage = (float*)sAhi;   // 64 x 136 floats
#pragma unroll
        for (int ct = 0; ct < 4; ct++)
            wmma::store_matrix_sync(stage + mrow * 136 + ncol + ct * 16, fc[ct], 136,
                                    wmma::mem_row_major);
        __syncthreads();

        // feat store + fused el/er
        for (int p = tid; p < 1024; p += 256) {
            int row = p >> 4, c8 = (p & 15) * 8;
            int gr = row0 + row;
            const float* s = stage + row * 136 + c8;
            float s0 = s[0], s1 = s[1], s2 = s[2], s3 = s[3];
            float s4 = s[4], s5 = s[5], s6 = s[6], s7 = s[7];
            if (gr < NN) {
                __half2 h0 = __floats2half2_rn(s0, s1);
                __half2 h1 = __floats2half2_rn(s2, s3);
                __half2 h2 = __floats2half2_rn(s4, s5);
                __half2 h3 = __floats2half2_rn(s6, s7);
                uint4 pack;
                pack.x = *(unsigned*)&h0; pack.y = *(unsigned*)&h1;
                pack.z = *(unsigned*)&h2; pack.w = *(unsigned*)&h3;
                *(uint4*)(feat + (size_t)gr * 128 + c8) = pack;
            }
            int h = c8 >> 5;
            const float* al8 = s_al + c8;
            const float* ar8 = s_ar + c8;
            float pl = s0 * al8[0] + s1 * al8[1] + s2 * al8[2] + s3 * al8[3]
                     + s4 * al8[4] + s5 * al8[5] + s6 * al8[6] + s7 * al8[7];
            float pr = s0 * ar8[0] + s1 * ar8[1] + s2 * ar8[2] + s3 * ar8[3]
                     + s4 * ar8[4] + s5 * ar8[5] + s6 * ar8[6] + s7 * ar8[7];
            pl += __shfl_xor_sync(0xffffffffu, pl, 1);
            pl += __shfl_xor_sync(0xffffffffu, pl, 2);
            pr += __shfl_xor_sync(0xffffffffu, pr, 1);
            pr += __shfl_xor_sync(0xffffffffu, pr, 2);
            if ((p & 3) == 0 && gr < NN) {
                el[gr * 4 + h] = pl;
                er[gr * 4 + h] = pr;
            }
        }
    }
}

// ---------------- fused softmax (max-free) + aggregation + BN stats ----------
template <bool RES, bool ACT>
__global__ void k_agg(const __half* __restrict__ feat, const float* __restrict__ hin,
                      const float4* __restrict__ el4, const float4* __restrict__ er4,
                      const float* __restrict__ snorm, const int* __restrict__ rowptr,
                      const int* __restrict__ csr, float* __restrict__ out,
                      float* __restrict__ bnstat, const float* __restrict__ pstat,
                      const float* __restrict__ pgamma, const float* __restrict__ pbeta) {
    __shared__ int   s_sj[8][32];
    __shared__ float s_a[8][32][4];
    __shared__ float bs[1024];
    __shared__ float bq[1024];
    __shared__ float psc[128], psh[128];
    int warp = threadIdx.x >> 5;
    int lane = threadIdx.x & 31;
    int node = blockIdx.x * 8 + warp;   // NN % 8 == 0
    if (RES) {
        int t = threadIdx.x;
        if (t < 128) {
            float mu = pstat[t] * (1.f / NN);
            float var = pstat[128 + t] * (1.f / NN) - mu * mu;
            float r = rsqrtf(var + 1e-5f);
            psc[t] = pgamma[t] * r;
            psh[t] = pbeta[t] - mu * pgamma[t] * r;
        }
        __syncthreads();
    }
    int start = rowptr[node], end = rowptr[node + 1];
    int deg = end - start;
    float4 er = er4[node];
    int hl = lane >> 3;
    int c0 = lane * 4;

    float4 acc = make_float4(0.f, 0.f, 0.f, 0.f);
    if (RES) {
        float4 h = *(const float4*)&hin[(size_t)node * 128 + c0];
        acc.x = eluf(h.x * psc[c0] + psh[c0]);
        acc.y = eluf(h.y * psc[c0 + 1] + psh[c0 + 1]);
        acc.z = eluf(h.z * psc[c0 + 2] + psh[c0 + 2]);
        acc.w = eluf(h.w * psc[c0 + 3] + psh[c0 + 3]);
    }

    if (deg <= 32) {
        bool on = lane < deg;
        int s = on ? csr[start + lane] : 0;
        float4 ex = make_float4(0.f, 0.f, 0.f, 0.f);
        if (on) {
            float4 e = el4[s];
            ex.x = __expf(lrelu(e.x + er.x));
            ex.y = __expf(lrelu(e.y + er.y));
            ex.z = __expf(lrelu(e.z + er.z));
            ex.w = __expf(lrelu(e.w + er.w));
        }
        float4 sm4 = ex;
#pragma unroll
        for (int o = 16; o > 0; o >>= 1) {
            sm4.x += __shfl_xor_sync(0xffffffffu, sm4.x, o);
            sm4.y += __shfl_xor_sync(0xffffffffu, sm4.y, o);
            sm4.z += __shfl_xor_sync(0xffffffffu, sm4.z, o);
            sm4.w += __shfl_xor_sync(0xffffffffu, sm4.w, o);
        }
        s_sj[warp][lane] = s;
        float4 aex = make_float4(ex.x / sm4.x, ex.y / sm4.y, ex.z / sm4.z, ex.w / sm4.w);
        *(float4*)&s_a[warp][lane][0] = aex;
        __syncwarp();
        int j = 0;
        for (; j + 4 <= deg; j += 4) {
            int sj0 = s_sj[warp][j],     sj1 = s_sj[warp][j + 1];
            int sj2 = s_sj[warp][j + 2], sj3 = s_sj[warp][j + 3];
            float a0 = s_a[warp][j][hl],     a1 = s_a[warp][j + 1][hl];
            float a2 = s_a[warp][j + 2][hl], a3 = s_a[warp][j + 3][hl];
            uint2 r0 = *(const uint2*)(feat + (size_t)sj0 * 128 + c0);
            uint2 r1 = *(const uint2*)(feat + (size_t)sj1 * 128 + c0);
            uint2 r2 = *(const uint2*)(feat + (size_t)sj2 * 128 + c0);
            uint2 r3 = *(const uint2*)(feat + (size_t)sj3 * 128 + c0);
            float2 p0 = __half22float2(*(__half2*)&r0.x), q0 = __half22float2(*(__half2*)&r0.y);
            float2 p1 = __half22float2(*(__half2*)&r1.x), q1 = __half22float2(*(__half2*)&r1.y);
            float2 p2 = __half22float2(*(__half2*)&r2.x), q2 = __half22float2(*(__half2*)&r2.y);
            float2 p3 = __half22float2(*(__half2*)&r3.x), q3 = __half22float2(*(__half2*)&r3.y);
            acc.x += p0.x * a0 + p1.x * a1 + p2.x * a2 + p3.x * a3;
            acc.y += p0.y * a0 + p1.y * a1 + p2.y * a2 + p3.y * a3;
            acc.z += q0.x * a0 + q1.x * a1 + q2.x * a2 + q3.x * a3;
            acc.w += q0.y * a0 + q1.y * a1 + q2.y * a2 + q3.y * a3;
        }
        for (; j < deg; j++) {
            int sj = s_sj[warp][j];
            float a = s_a[warp][j][hl];
            uint2 raw = *(const uint2*)(feat + (size_t)sj * 128 + c0);
            float2 f01 = __half22float2(*(__half2*)&raw.x);
            float2 f23 = __half22float2(*(__half2*)&raw.y);
            acc.x += f01.x * a; acc.y += f01.y * a;
            acc.z += f23.x * a; acc.w += f23.y * a;
        }
    } else {
        float s0 = 0.f, s1 = 0.f, s2 = 0.f, s3 = 0.f;
        for (int k = start + lane; k < end; k += 32) {
            int s = csr[k];
            float4 e = el4[s];
            s0 += __expf(lrelu(e.x + er.x));
            s1 += __expf(lrelu(e.y + er.y));
            s2 += __expf(lrelu(e.z + er.z));
            s3 += __expf(lrelu(e.w + er.w));
        }
#pragma unroll
        for (int o = 16; o > 0; o >>= 1) {
            s0 += __shfl_xor_sync(0xffffffffu, s0, o);
            s1 += __shfl_xor_sync(0xffffffffu, s1, o);
            s2 += __shfl_xor_sync(0xffffffffu, s2, o);
            s3 += __shfl_xor_sync(0xffffffffu, s3, o);
        }
        float invh = 1.f / (hl == 0 ? s0 : hl == 1 ? s1 : hl == 2 ? s2 : s3);
        float erh = hl == 0 ? er.x : hl == 1 ? er.y : hl == 2 ? er.z : er.w;
        int k = start;
        for (; k + 4 <= end; k += 4) {
            int sj0 = csr[k], sj1 = csr[k + 1], sj2 = csr[k + 2], sj3 = csr[k + 3];
            float4 e0 = el4[sj0], e1 = el4[sj1], e2 = el4[sj2], e3 = el4[sj3];
            float ev0 = hl == 0 ? e0.x : hl == 1 ? e0.y : hl == 2 ? e0.z : e0.w;
            float ev1 = hl == 0 ? e1.x : hl == 1 ? e1.y : hl == 2 ? e1.z : e1.w;
            float ev2 = hl == 0 ? e2.x : hl == 1 ? e2.y : hl == 2 ? e2.z : e2.w;
            float ev3 = hl == 0 ? e3.x : hl == 1 ? e3.y : hl == 2 ? e3.z : e3.w;
            float a0 = __expf(lrelu(ev0 + erh)) * invh;
            float a1 = __expf(lrelu(ev1 + erh)) * invh;
            float a2 = __expf(lrelu(ev2 + erh)) * invh;
            float a3 = __expf(lrelu(ev3 + erh)) * invh;
            uint2 r0 = *(const uint2*)(feat + (size_t)sj0 * 128 + c0);
            uint2 r1 = *(const uint2*)(feat + (size_t)sj1 * 128 + c0);
            uint2 r2 = *(const uint2*)(feat + (size_t)sj2 * 128 + c0);
            uint2 r3 = *(const uint2*)(feat + (size_t)sj3 * 128 + c0);
            float2 p0 = __half22float2(*(__half2*)&r0.x), q0 = __half22float2(*(__half2*)&r0.y);
            float2 p1 = __half22float2(*(__half2*)&r1.x), q1 = __half22float2(*(__half2*)&r1.y);
            float2 p2 = __half22float2(*(__half2*)&r2.x), q2 = __half22float2(*(__half2*)&r2.y);
            float2 p3 = __half22float2(*(__half2*)&r3.x), q3 = __half22float2(*(__half2*)&r3.y);
            acc.x += p0.x * a0 + p1.x * a1 + p2.x * a2 + p3.x * a3;
            acc.y += p0.y * a0 + p1.y * a1 + p2.y * a2 + p3.y * a3;
            acc.z += q0.x * a0 + q1.x * a1 + q2.x * a2 + q3.x * a3;
            acc.w += q0.y * a0 + q1.y * a1 + q2.y * a2 + q3.y * a3;
        }
        for (; k < end; k++) {
            int s = csr[k];
            float4 e = el4[s];
            float ev = hl == 0 ? e.x : hl == 1 ? e.y : hl == 2 ? e.z : e.w;
            float a = __expf(lrelu(ev + erh)) * invh;
            uint2 raw = *(const uint2*)(feat + (size_t)s * 128 + c0);
            float2 f01 = __half22float2(*(__half2*)&raw.x);
            float2 f23 = __half22float2(*(__half2*)&raw.y);
            acc.x += f01.x * a; acc.y += f01.y * a;
            acc.z += f23.x * a; acc.w += f23.y * a;
        }
    }
    if (ACT) {
        acc.x = eluf(acc.x); acc.y = eluf(acc.y);
        acc.z = eluf(acc.z); acc.w = eluf(acc.w);
    }
    float sn = snorm[node];
    acc.x *= sn; acc.y *= sn; acc.z *= sn; acc.w *= sn;
    *(float4*)&out[(size_t)node * 128 + c0] = acc;

    ((float4*)bs)[warp * 32 + lane] = acc;
    ((float4*)bq)[warp * 32 + lane] =
        make_float4(acc.x * acc.x, acc.y * acc.y, acc.z * acc.z, acc.w * acc.w);
    __syncthreads();
    int t = threadIdx.x;
    if (t < 128) {
        float s = 0.f, q = 0.f;
#pragma unroll
        for (int w = 0; w < 8; w++) { s += bs[w * 128 + t]; q += bq[w * 128 + t]; }
        atomicAdd(&bnstat[t], s);
        atomicAdd(&bnstat[128 + t], q);
    }
}

// -------- persistent classifier: HMMA 128->64 (A split, W fp16), then 64->2 --
__global__ void k_cls(const float* __restrict__ H, const float* __restrict__ w1,
                      const float* __restrict__ b1, const float* __restrict__ w2,
                      const float* __restrict__ b2, const float* __restrict__ stat,
                      const float* __restrict__ gamma, const float* __restrict__ beta,
                      float* __restrict__ out) {
    extern __shared__ __half smh[];
    __half* sW   = smh;                  // 128 x 72
    __half* sAhi = sW + 128 * 72;        // 64 x 136
    __half* sAlo = sAhi + 64 * 136;      // 64 x 136
    __shared__ float sc[128], shf[128];
    __shared__ float sb1[64];
    __shared__ float sw2[128];
    int tid = threadIdx.x, warp = tid >> 5;
    if (tid < 128) {
        float mu = stat[tid] * (1.f / NN);
        float var = stat[128 + tid] * (1.f / NN) - mu * mu;
        float r = rsqrtf(var + 1e-5f);
        sc[tid] = gamma[tid] * r;
        shf[tid] = beta[tid] - mu * gamma[tid] * r;
    }
    if (tid < 64) sb1[tid] = b1[tid];
    if (tid < 128) sw2[tid] = w2[tid];

    // load + round W once per block
    for (int p = tid; p < 2048; p += 256) {
        int r = p >> 4, c = (p & 15) * 4;
        float4 v = *(const float4*)&w1[(size_t)r * 64 + c];
        sW[r * 72 + c]     = __float2half_rn(v.x);
        sW[r * 72 + c + 1] = __float2half_rn(v.y);
        sW[r * 72 + c + 2] = __float2half_rn(v.z);
        sW[r * 72 + c + 3] = __float2half_rn(v.w);
    }

    int mrow = (warp & 3) * 16;
    int ncol = (warp >> 2) * 32;

    for (int tile = blockIdx.x; tile < NTILES; tile += gridDim.x) {
        int row0 = tile * 64;
        __syncthreads();   // W/consts ready (1st) / stage consumed (later)
        for (int p = tid; p < 2048; p += 256) {
            int row = p >> 5, c = (p & 31) * 4;
            int gr = row0 + row;
            float4 v = make_float4(0.f, 0.f, 0.f, 0.f);
            if (gr < NN) {
                v = *(const float4*)&H[(size_t)gr * 128 + c];
                v.x = eluf(v.x * sc[c] + shf[c]);
                v.y = eluf(v.y * sc[c + 1] + shf[c + 1]);
                v.z = eluf(v.z * sc[c + 2] + shf[c + 2]);
                v.w = eluf(v.w * sc[c + 3] + shf[c + 3]);
            }
            split2h(v.x, sAhi[row * 136 + c], sAlo[row * 136 + c]);
            split2h(v.y, sAhi[row * 136 + c + 1], sAlo[row * 136 + c + 1]);
            split2h(v.z, sAhi[row * 136 + c + 2], sAlo[row * 136 + c + 2]);
            split2h(v.w, sAhi[row * 136 + c + 3], sAlo[row * 136 + c + 3]);
        }
        __syncthreads();

        wmma::fragment<wmma::accumulator, 16, 16, 16, float> fc[2];
#pragma unroll
        for (int i = 0; i < 2; i++) wmma::fill_fragment(fc[i], 0.f);
#pragma unroll
        for (int ks = 0; ks < 8; ks++) {
            wmma::fragment<wmma::matrix_a, 16, 16, 16, __half, wmma::row_major> fah, fal;
            wmma::load_matrix_sync(fah, sAhi + mrow * 136 + ks * 16, 136);
            wmma::load_matrix_sync(fal, sAlo + mrow * 136 + ks * 16, 136);
#pragma unroll
            for (int ct = 0; ct < 2; ct++) {
                wmma::fragment<wmma::matrix_b, 16, 16, 16, __half, wmma::row_major> fb;
                wmma::load_matrix_sync(fb, sW + (ks * 16) * 72 + ncol + ct * 16, 72);
                wmma::mma_sync(fc[ct], fah, fb, fc[ct]);
                wmma::mma_sync(fc[ct], fal, fb, fc[ct]);
            }
        }
        __syncthreads();   // A reads done
        float* stage = (float*)sAhi;  // 64 x 72 (fits in A buffers)
#pragma unroll
        for (int ct = 0; ct < 2; ct++)
            wmma::store_matrix_sync(stage + mrow * 72 + ncol + ct * 16, fc[ct], 72,
                                    wmma::mem_row_major);
        __syncthreads();
        if (tid < 128) {
            int row = tid >> 1, o = tid & 1;
            int gr = row0 + row;
            if (gr < NN) {
                float s = b2[o];
                for (int k = 0; k < 64; k++) {
                    float hv = stage[row * 72 + k] + sb1[k];
                    hv = hv > 0.f ? hv : 0.f;
                    s += hv * sw2[k * 2 + o];
                }
                out[(size_t)gr * 2 + o] = s;
            }
        }
    }
}

// ---------------- host orchestration -----------------------------------------
extern "C" void kernel_launch(void* const* d_in, const int* in_sizes, int n_in,
                              void* d_out, int out_size) {
    const int* x = (const int*)d_in[0];
    const int* src = (const int*)d_in[1];
    const int* dst = (const int*)d_in[2];
    const float* snorm_n = (const float*)d_in[3];
    const float* embed = (const float*)d_in[5];
    const float* W[3] = {(const float*)d_in[6], (const float*)d_in[11], (const float*)d_in[16]};
    const float* al[3] = {(const float*)d_in[7], (const float*)d_in[12], (const float*)d_in[17]};
    const float* ar[3] = {(const float*)d_in[8], (const float*)d_in[13], (const float*)d_in[18]};
    const float* gamma[3] = {(const float*)d_in[9], (const float*)d_in[14], (const float*)d_in[19]};
    const float* beta[3] = {(const float*)d_in[10], (const float*)d_in[15], (const float*)d_in[20]};
    const float* cls1_w = (const float*)d_in[21];
    const float* cls1_b = (const float*)d_in[22];
    const float* cls2_w = (const float*)d_in[23];
    const float* cls2_b = (const float*)d_in[24];
    float* out = (float*)d_out;

    float *h0, *h1, *el, *er, *bnstat;
    __half* feath;
    int *deg, *rowptr, *cursor, *csr, *partial, *poff;
    cudaGetSymbolAddress((void**)&h0, g_h0);
    cudaGetSymbolAddress((void**)&h1, g_h1);
    cudaGetSymbolAddress((void**)&feath, g_feath);
    cudaGetSymbolAddress((void**)&el, g_el);
    cudaGetSymbolAddress((void**)&er, g_er);
    cudaGetSymbolAddress((void**)&bnstat, g_bnstat);
    cudaGetSymbolAddress((void**)&deg, g_deg);
    cudaGetSymbolAddress((void**)&rowptr, g_rowptr);
    cudaGetSymbolAddress((void**)&cursor, g_cursor);
    cudaGetSymbolAddress((void**)&csr, g_csr);
    cudaGetSymbolAddress((void**)&partial, g_partial);
    cudaGetSymbolAddress((void**)&poff, g_poff);

    const int GEMM_SMEM = (128 * 136 + 2 * 64 * 136) * 2;  // 69632
    const int CLS_SMEM  = (128 * 72 + 2 * 64 * 136) * 2;   // 53248
    static bool attr_done = false;
    static cudaStream_t s2 = nullptr;
    static cudaEvent_t evFork = nullptr, evJoin = nullptr;
    if (!attr_done) {
        cudaFuncSetAttribute(k_gemm<true>, cudaFuncAttributeMaxDynamicSharedMemorySize, GEMM_SMEM);
        cudaFuncSetAttribute(k_gemm<false>, cudaFuncAttributeMaxDynamicSharedMemorySize, GEMM_SMEM);
        cudaFuncSetAttribute(k_cls, cudaFuncAttributeMaxDynamicSharedMemorySize, CLS_SMEM);
        cudaStreamCreateWithFlags(&s2, cudaStreamNonBlocking);
        cudaEventCreateWithFlags(&evFork, cudaEventDisableTiming);
        cudaEventCreateWithFlags(&evJoin, cudaEventDisableTiming);
        attr_done = true;
    }
    const int NSCAN = (NN + 255) / 256;  // 196

    // Fork: CSR build on side stream, overlapped with layer-0 GEMM on main.
    cudaEventRecord(evFork, 0);
    cudaStreamWaitEvent(s2, evFork, 0);
    cudaMemsetAsync(deg, 0, NN * sizeof(int), s2);
    k_hist<<<(EE + 255) / 256, 256, 0, s2>>>(dst, deg);
    k_scan1<<<NSCAN, 256, 0, s2>>>(deg, partial);
    k_scan2<<<1, 256, 0, s2>>>(partial, poff, NSCAN);
    k_scan3<<<NSCAN, 256, 0, s2>>>(deg, poff, rowptr, cursor);
    k_fill<<<(EE + 255) / 256, 256, 0, s2>>>(src, dst, cursor, csr);
    cudaEventRecord(evJoin, s2);

    // Main stream: layer-0 GEMM (independent of CSR).
    cudaMemsetAsync(bnstat, 0, 3 * 256 * sizeof(float), 0);
    k_gemm<true><<<PGRID, 256, GEMM_SMEM>>>(nullptr, x, embed, W[0],
                                            nullptr, nullptr, nullptr,
                                            al[0], ar[0], feath, el, er);
    cudaStreamWaitEvent(0, evJoin, 0);

    k_agg<false, false><<<NN / 8, 256>>>(feath, nullptr, (const float4*)el,
                                         (const float4*)er, snorm_n, rowptr, csr,
                                         h0, &bnstat[0], nullptr, nullptr, nullptr);
    // layer 1
    k_gemm<false><<<PGRID, 256, GEMM_SMEM>>>(h0, nullptr, nullptr, W[1],
                                             &bnstat[0], gamma[0], beta[0],
                                             al[1], ar[1], feath, el, er);
    k_agg<true, true><<<NN / 8, 256>>>(feath, h0, (const float4*)el,
                                       (const float4*)er, snorm_n, rowptr, csr,
                                       h1, &bnstat[256], &bnstat[0], gamma[0], beta[0]);
    // layer 2
    k_gemm<false><<<PGRID, 256, GEMM_SMEM>>>(h1, nullptr, nullptr, W[2],
                                             &bnstat[256], gamma[1], beta[1],
                                             al[2], ar[2], feath, el, er);
    k_agg<true, true><<<NN / 8, 256>>>(feath, h1, (const float4*)el,
                                       (const float4*)er, snorm_n, rowptr, csr,
                                       h0, &bnstat[512], &bnstat[256], gamma[1], beta[1]);
    // classifier (persistent)
    k_cls<<<PGRID, 256, CLS_SMEM>>>(h0, cls1_w, cls1_b, cls2_w, cls2_b,
                                    &bnstat[512], gamma[2], beta[2], out);
}